// round 1
// baseline (speedup 1.0000x reference)
#include <cuda_runtime.h>
#include <math.h>

#define BATCH 2
#define SEQ   2048
#define DIM   512
#define NHEAD 8
#define DK    64
#define NEGV  (-1e9f)

// Scratch (alloc-free, graph-capturable)
__device__ float g_Q[BATCH*SEQ*DIM];
__device__ float g_K[BATCH*SEQ*DIM];
__device__ float g_V[BATCH*SEQ*DIM];
__device__ float g_O[BATCH*SEQ*DIM];

// ---------------------------------------------------------------------------
// Y[m,n] = sum_k X[m,k] * W[n,k]   (y = x @ W^T),  M=4096, N=512, K=512
// 64x64 block tile, 32 k-tile, 256 threads, 4x4 micro-tile per thread.
// xsel==1 -> X = g_O ; ysel in {0,1,2} -> Y = g_Q/g_K/g_V, else Yext.
// ---------------------------------------------------------------------------
__global__ __launch_bounds__(256) void gemm_xwt(const float* __restrict__ Xext,
                                                const float* __restrict__ W,
                                                float* __restrict__ Yext,
                                                int xsel, int ysel)
{
    const float* X = (xsel == 1) ? g_O : Xext;
    float* Y = (ysel == 0) ? g_Q : (ysel == 1) ? g_K : (ysel == 2) ? g_V : Yext;

    const int M = BATCH*SEQ, N = DIM, K = DIM;
    __shared__ float As[64][33];   // [m][k]
    __shared__ float Bt[32][68];   // [k][n]

    int tid = threadIdx.x;
    int tx = tid & 15, ty = tid >> 4;
    int m0 = blockIdx.x * 64, n0 = blockIdx.y * 64;

    float acc[4][4];
    #pragma unroll
    for (int i = 0; i < 4; i++)
        #pragma unroll
        for (int j = 0; j < 4; j++) acc[i][j] = 0.f;

    for (int k0 = 0; k0 < K; k0 += 32) {
        #pragma unroll
        for (int q = 0; q < 8; q++) {
            int idx = tid + q * 256;
            int r = idx >> 5, c = idx & 31;
            As[r][c] = X[(size_t)(m0 + r) * K + k0 + c];
            Bt[c][r] = W[(size_t)(n0 + r) * K + k0 + c];
        }
        __syncthreads();
        #pragma unroll
        for (int kk = 0; kk < 32; kk++) {
            float a[4];
            #pragma unroll
            for (int i = 0; i < 4; i++) a[i] = As[ty*4 + i][kk];
            float4 bv = *(const float4*)&Bt[kk][tx*4];
            #pragma unroll
            for (int i = 0; i < 4; i++) {
                acc[i][0] += a[i] * bv.x;
                acc[i][1] += a[i] * bv.y;
                acc[i][2] += a[i] * bv.z;
                acc[i][3] += a[i] * bv.w;
            }
        }
        __syncthreads();
    }

    #pragma unroll
    for (int i = 0; i < 4; i++) {
        float4 o = make_float4(acc[i][0], acc[i][1], acc[i][2], acc[i][3]);
        *(float4*)&Y[(size_t)(m0 + ty*4 + i) * N + n0 + tx*4] = o;
    }
    (void)M;
}

// ---------------------------------------------------------------------------
// Flash-style attention per (b,h): 64-row i-tiles, sweep 64-col j-tiles.
// Online softmax carries exact -1e9 for masked entries (matches reference,
// including fully-masked rows -> uniform softmax).
// Smem: Qs + Xs(K^T then P, XOR-swizzled) + Vs = exactly 48KB static.
// ---------------------------------------------------------------------------
#define XSW(r, c) ((r)*64 + ((c) ^ (((r) & 7) << 2)))

__global__ __launch_bounds__(256) void attn_kernel(const int* __restrict__ seq_mask,
                                                   const int* __restrict__ sparse_masks)
{
    __shared__ float Qs[64*64];   // [i][d]
    __shared__ float Xs[64*64];   // K^T [d][j] swizzled, reused as P [i][j] swizzled
    __shared__ float Vs[64*64];   // [j][d]

    int tid = threadIdx.x;
    int tx = tid & 15, ty = tid >> 4;
    int i0 = blockIdx.x * 64;
    int bh = blockIdx.y;
    int b = bh >> 3, h = bh & 7;

    const float* Qg = g_Q + ((size_t)(b*SEQ + i0)) * DIM + h*DK;
    const float* Kg = g_K + ((size_t)(b*SEQ)) * DIM + h*DK;
    const float* Vg = g_V + ((size_t)(b*SEQ)) * DIM + h*DK;
    const int* smg = seq_mask    + (size_t)b * SEQ * SEQ;
    const int* hmg = sparse_masks + (size_t)(h & 1) * SEQ * SEQ;

    // Load Q tile (coalesced; broadcast-read layout, no pad needed)
    #pragma unroll
    for (int q = 0; q < 16; q++) {
        int idx = tid + q * 256;
        int r = idx >> 6, c = idx & 63;
        Qs[r*64 + c] = Qg[(size_t)r * DIM + c];
    }

    float m[4], l[4], acc[4][4];
    #pragma unroll
    for (int i = 0; i < 4; i++) {
        m[i] = -INFINITY; l[i] = 0.f;
        #pragma unroll
        for (int j = 0; j < 4; j++) acc[i][j] = 0.f;
    }

    for (int j0 = 0; j0 < SEQ; j0 += 64) {
        __syncthreads();   // previous PV done reading Xs(P) / Vs
        // Load K^T (swizzled transpose) and V
        #pragma unroll
        for (int q = 0; q < 16; q++) {
            int idx = tid + q * 256;
            int r = idx >> 6, c = idx & 63;          // r = local j, c = d
            Xs[XSW(c, r)] = Kg[(size_t)(j0 + r) * DIM + c];
            Vs[r*64 + c]  = Vg[(size_t)(j0 + r) * DIM + c];
        }
        __syncthreads();

        // S = Q * K^T  (4x4 per thread)
        float s[4][4];
        #pragma unroll
        for (int i = 0; i < 4; i++)
            #pragma unroll
            for (int j = 0; j < 4; j++) s[i][j] = 0.f;

        #pragma unroll 16
        for (int d = 0; d < 64; d++) {
            float a[4];
            #pragma unroll
            for (int i = 0; i < 4; i++) a[i] = Qs[(ty*4 + i)*64 + d];
            float4 bv = *(const float4*)&Xs[XSW(d, tx*4)];
            #pragma unroll
            for (int i = 0; i < 4; i++) {
                s[i][0] += a[i] * bv.x;
                s[i][1] += a[i] * bv.y;
                s[i][2] += a[i] * bv.z;
                s[i][3] += a[i] * bv.w;
            }
        }
        __syncthreads();   // all done reading K^T; Xs now reusable for P

        // Masks + online softmax + write P
        #pragma unroll
        for (int i = 0; i < 4; i++) {
            int gi = i0 + ty*4 + i;
            int4 sm = *(const int4*)&smg[(size_t)gi * SEQ + j0 + tx*4];
            int4 hm = *(const int4*)&hmg[(size_t)gi * SEQ + j0 + tx*4];
            s[i][0] = (sm.x & hm.x) ? s[i][0] * 0.125f : NEGV;
            s[i][1] = (sm.y & hm.y) ? s[i][1] * 0.125f : NEGV;
            s[i][2] = (sm.z & hm.z) ? s[i][2] * 0.125f : NEGV;
            s[i][3] = (sm.w & hm.w) ? s[i][3] * 0.125f : NEGV;

            float mx = fmaxf(fmaxf(s[i][0], s[i][1]), fmaxf(s[i][2], s[i][3]));
            #pragma unroll
            for (int o = 8; o > 0; o >>= 1)
                mx = fmaxf(mx, __shfl_xor_sync(0xffffffffu, mx, o));

            float mn = fmaxf(m[i], mx);
            float corr = __expf(m[i] - mn);       // exp(-inf)=0 on first tile
            float p0 = __expf(s[i][0] - mn);
            float p1 = __expf(s[i][1] - mn);
            float p2 = __expf(s[i][2] - mn);
            float p3 = __expf(s[i][3] - mn);
            float rs = p0 + p1 + p2 + p3;
            #pragma unroll
            for (int o = 8; o > 0; o >>= 1)
                rs += __shfl_xor_sync(0xffffffffu, rs, o);

            l[i] = l[i] * corr + rs;
            m[i] = mn;
            acc[i][0] *= corr; acc[i][1] *= corr; acc[i][2] *= corr; acc[i][3] *= corr;

            int r = ty*4 + i;
            *(float4*)&Xs[XSW(r, tx*4)] = make_float4(p0, p1, p2, p3);
        }
        __syncthreads();

        // O += P * V
        #pragma unroll 16
        for (int jj = 0; jj < 64; jj++) {
            float4 v = *(const float4*)&Vs[jj*64 + tx*4];
            #pragma unroll
            for (int i = 0; i < 4; i++) {
                int r = ty*4 + i;
                float p = Xs[r*64 + (jj ^ ((r & 7) << 2))];
                acc[i][0] += p * v.x;
                acc[i][1] += p * v.y;
                acc[i][2] += p * v.z;
                acc[i][3] += p * v.w;
            }
        }
    }

    float* Og = g_O + ((size_t)(b*SEQ + i0)) * DIM + h*DK;
    #pragma unroll
    for (int i = 0; i < 4; i++) {
        float inv = 1.0f / l[i];
        *(float4*)&Og[(size_t)(ty*4 + i) * DIM + tx*4] =
            make_float4(acc[i][0]*inv, acc[i][1]*inv, acc[i][2]*inv, acc[i][3]*inv);
    }
}

// ---------------------------------------------------------------------------
extern "C" void kernel_launch(void* const* d_in, const int* in_sizes, int n_in,
                              void* d_out, int out_size)
{
    const float* x  = (const float*)d_in[0];
    const float* Wq = (const float*)d_in[1];
    const float* Wk = (const float*)d_in[2];
    const float* Wv = (const float*)d_in[3];
    const float* Wo = (const float*)d_in[4];
    const int* seq_mask     = (const int*)d_in[5];
    const int* sparse_masks = (const int*)d_in[6];
    float* out = (float*)d_out;

    dim3 gg(BATCH*SEQ / 64, DIM / 64);   // (64, 8)
    gemm_xwt<<<gg, 256>>>(x, Wq, nullptr, 0, 0);   // -> g_Q
    gemm_xwt<<<gg, 256>>>(x, Wk, nullptr, 0, 1);   // -> g_K
    gemm_xwt<<<gg, 256>>>(x, Wv, nullptr, 0, 2);   // -> g_V

    attn_kernel<<<dim3(SEQ / 64, BATCH * NHEAD), 256>>>(seq_mask, sparse_masks);

    gemm_xwt<<<gg, 256>>>(nullptr, Wo, out, 1, 3); // g_O @ Wo^T -> out
    (void)in_sizes; (void)n_in; (void)out_size;
}

// round 2
// speedup vs baseline: 1.2273x; 1.2273x over previous
#include <cuda_runtime.h>
#include <math.h>

#define BATCH 2
#define SEQ   2048
#define DIM   512
#define NHEAD 8
#define DK    64
#define NEGV  (-1e9f)

typedef unsigned long long u64;
typedef unsigned int u32;

// Scratch (alloc-free, graph-capturable)
__device__ float g_Q[BATCH*SEQ*DIM];
__device__ float g_K[BATCH*SEQ*DIM];
__device__ float g_V[BATCH*SEQ*DIM];
__device__ float g_O[BATCH*SEQ*DIM];
__device__ u32   g_mask[4*SEQ*(SEQ/32)];   // [b*2+par][row][j-word]

// ---- packed fp32 (Blackwell FFMA2) helpers -------------------------------
#define FMA2(d,a,b,c) asm("fma.rn.f32x2 %0, %1, %2, %3;" : "=l"(d) : "l"(a), "l"(b), "l"(c))
#define MUL2(d,a,b)   asm("mul.rn.f32x2 %0, %1, %2;"     : "=l"(d) : "l"(a), "l"(b))
#define PACK2(d,x)    asm("mov.b64 %0, {%1, %1};" : "=l"(d) : "r"(__float_as_uint(x)))
#define PACKAB(d,x,y) asm("mov.b64 %0, {%1, %2};" : "=l"(d) : "r"(__float_as_uint(x)), "r"(__float_as_uint(y)))

static __device__ __forceinline__ float2 unpack2(u64 v) {
    float2 f;
    asm("mov.b64 {%0, %1}, %2;" : "=f"(f.x), "=f"(f.y) : "l"(v));
    return f;
}

// ---------------------------------------------------------------------------
// Precompute combined masks as bit tables: combo c = b*2 + (h&1)
// bit j of word w (j = w*32 + lane) = seq_mask[b][i][j] & sparse_masks[par][i][j]
// ---------------------------------------------------------------------------
__global__ void mask_prep(const int* __restrict__ seq_mask,
                          const int* __restrict__ sparse_masks)
{
    int row  = (blockIdx.x * blockDim.x + threadIdx.x) >> 5;
    int lane = threadIdx.x & 31;
    if (row >= SEQ) return;
    const int* s0 = seq_mask     + (size_t)0*SEQ*SEQ + (size_t)row*SEQ;
    const int* s1 = seq_mask     + (size_t)1*SEQ*SEQ + (size_t)row*SEQ;
    const int* p0 = sparse_masks + (size_t)0*SEQ*SEQ + (size_t)row*SEQ;
    const int* p1 = sparse_masks + (size_t)1*SEQ*SEQ + (size_t)row*SEQ;
    for (int w = 0; w < SEQ/32; w++) {
        int j = w*32 + lane;
        int a0 = s0[j], a1 = s1[j], b0 = p0[j], b1 = p1[j];
        u32 m00 = __ballot_sync(0xffffffffu, (a0 & b0) != 0);
        u32 m01 = __ballot_sync(0xffffffffu, (a0 & b1) != 0);
        u32 m10 = __ballot_sync(0xffffffffu, (a1 & b0) != 0);
        u32 m11 = __ballot_sync(0xffffffffu, (a1 & b1) != 0);
        if (lane == 0) {
            g_mask[((size_t)0*SEQ + row)*(SEQ/32) + w] = m00;
            g_mask[((size_t)1*SEQ + row)*(SEQ/32) + w] = m01;
            g_mask[((size_t)2*SEQ + row)*(SEQ/32) + w] = m10;
            g_mask[((size_t)3*SEQ + row)*(SEQ/32) + w] = m11;
        }
    }
}

// ---------------------------------------------------------------------------
// GEMM: Y[m,n] = sum_k X[m,k]*W[n,k]  (y = x@W^T), M=4096, N=K=512.
// 64x64 tile, 128 threads, 8x4 micro-tile, FFMA2 packed over row pairs.
// ---------------------------------------------------------------------------
#define ASW(k,m) ((k)*64 + ((m) ^ ((((k)>>1)&15)<<2)))

__global__ __launch_bounds__(128) void gemm_xwt(const float* __restrict__ Xext,
                                                const float* __restrict__ W,
                                                float* __restrict__ Yext,
                                                int xsel, int ysel)
{
    const float* X = (xsel == 1) ? g_O : Xext;
    float* Y = (ysel == 0) ? g_Q : (ysel == 1) ? g_K : (ysel == 2) ? g_V : Yext;

    __shared__ float As[32*64];    // [k][m], swizzled
    __shared__ float Bs[32][68];   // [k][n]

    int tid = threadIdx.x;
    int tx = tid & 15, ty = tid >> 4;          // j = 4*tx, i = 8*ty
    int m0 = blockIdx.x * 64, n0 = blockIdx.y * 64;

    u64 acc[4][4];
    #pragma unroll
    for (int a = 0; a < 4; a++)
        #pragma unroll
        for (int b = 0; b < 4; b++) acc[a][b] = 0ULL;

    for (int k0 = 0; k0 < DIM; k0 += 32) {
        #pragma unroll
        for (int q = 0; q < 16; q++) {
            int idx = tid + q*128;
            int r = idx >> 5, c = idx & 31;     // r: tile row, c: k
            As[ASW(c, r)] = X[(size_t)(m0 + r)*DIM + k0 + c];
            Bs[c][r]      = W[(size_t)(n0 + r)*DIM + k0 + c];
        }
        __syncthreads();
        #pragma unroll
        for (int kk = 0; kk < 32; kk++) {
            ulonglong2 aA = *(const ulonglong2*)&As[ASW(kk, ty*8)];
            ulonglong2 aB = *(const ulonglong2*)&As[ASW(kk, ty*8 + 4)];
            float4 bv = *(const float4*)&Bs[kk][tx*4];
            u64 b0, b1, b2, b3;
            PACK2(b0, bv.x); PACK2(b1, bv.y); PACK2(b2, bv.z); PACK2(b3, bv.w);
            u64 av[4] = {aA.x, aA.y, aB.x, aB.y};
            #pragma unroll
            for (int i2 = 0; i2 < 4; i2++) {
                FMA2(acc[i2][0], av[i2], b0, acc[i2][0]);
                FMA2(acc[i2][1], av[i2], b1, acc[i2][1]);
                FMA2(acc[i2][2], av[i2], b2, acc[i2][2]);
                FMA2(acc[i2][3], av[i2], b3, acc[i2][3]);
            }
        }
        __syncthreads();
    }

    #pragma unroll
    for (int i2 = 0; i2 < 4; i2++) {
        float2 c0 = unpack2(acc[i2][0]);
        float2 c1 = unpack2(acc[i2][1]);
        float2 c2 = unpack2(acc[i2][2]);
        float2 c3 = unpack2(acc[i2][3]);
        size_t r0 = (size_t)(m0 + ty*8 + 2*i2) * DIM + n0 + tx*4;
        *(float4*)&Y[r0]       = make_float4(c0.x, c1.x, c2.x, c3.x);
        *(float4*)&Y[r0 + DIM] = make_float4(c0.y, c1.y, c2.y, c3.y);
    }
}

// ---------------------------------------------------------------------------
// Flash attention, 64x64 tiles, 128 threads, 8x4 micro-tile, FFMA2.
// Qs: Q^T [d][i] swizzled. Xs: K^T [d][j] swizzled, reused as P^T [j][i].
// Vs: [j][d] row-major. 48KB static smem.
// ---------------------------------------------------------------------------
#define QSW(d,i) ((d)*64 + ((i) ^ (((d)&7)<<2)))
#define KSW(d,j) ((d)*64 + ((j) ^ ((((d)>>1)&15)<<2)))
#define PSW(j,i) ((j)*64 + ((i) ^ ((((j)>>2)&15)<<1)))

__global__ __launch_bounds__(128, 4) void attn_kernel()
{
    __shared__ float Qs[64*64];
    __shared__ float Xs[64*64];
    __shared__ float Vs[64*64];

    int tid = threadIdx.x;
    int tx = tid & 15, ty = tid >> 4;          // j = 4*tx, i = 8*ty
    int i0 = blockIdx.x * 64;
    int bh = blockIdx.y;
    int b = bh >> 3, h = bh & 7;

    const float* Qg = g_Q + (size_t)(b*SEQ + i0)*DIM + h*DK;
    const float* Kg = g_K + (size_t)(b*SEQ)*DIM + h*DK;
    const float* Vg = g_V + (size_t)(b*SEQ)*DIM + h*DK;
    const u32*   Mg = g_mask + (size_t)(b*2 + (h & 1)) * SEQ * (SEQ/32);

    // Load Q transposed (swizzled), scalar coalesced
    #pragma unroll
    for (int q = 0; q < 32; q++) {
        int idx = tid + q*128;
        int r = idx >> 6, c = idx & 63;        // r = i, c = d
        Qs[QSW(c, r)] = Qg[(size_t)r*DIM + c];
    }

    float m[8], l[8];
    u64 acc[4][4];
    #pragma unroll
    for (int i = 0; i < 8; i++) { m[i] = -INFINITY; l[i] = 0.f; }
    #pragma unroll
    for (int a = 0; a < 4; a++)
        #pragma unroll
        for (int c = 0; c < 4; c++) acc[a][c] = 0ULL;

    for (int j0 = 0; j0 < SEQ; j0 += 64) {
        __syncthreads();   // prior iter done with Xs(P)/Vs; also covers Q load
        // K transposed (swizzled, scalar), V row-major (float4)
        #pragma unroll
        for (int q = 0; q < 32; q++) {
            int idx = tid + q*128;
            int r = idx >> 6, c = idx & 63;    // r = local j, c = d
            Xs[KSW(c, r)] = Kg[(size_t)(j0 + r)*DIM + c];
        }
        #pragma unroll
        for (int q = 0; q < 8; q++) {
            int idx = tid + q*128;
            int r = idx >> 4, c4 = idx & 15;
            *(float4*)&Vs[r*64 + c4*4] = *(const float4*)&Vg[(size_t)(j0 + r)*DIM + c4*4];
        }
        __syncthreads();

        // S = Q K^T (packed over i-pairs)
        u64 s2[4][4];
        #pragma unroll
        for (int a = 0; a < 4; a++)
            #pragma unroll
            for (int c = 0; c < 4; c++) s2[a][c] = 0ULL;

        #pragma unroll 8
        for (int d = 0; d < 64; d++) {
            ulonglong2 aA = *(const ulonglong2*)&Qs[QSW(d, ty*8)];
            ulonglong2 aB = *(const ulonglong2*)&Qs[QSW(d, ty*8 + 4)];
            float4 bv = *(const float4*)&Xs[KSW(d, tx*4)];
            u64 b0, b1, b2, b3;
            PACK2(b0, bv.x); PACK2(b1, bv.y); PACK2(b2, bv.z); PACK2(b3, bv.w);
            u64 av[4] = {aA.x, aA.y, aB.x, aB.y};
            #pragma unroll
            for (int i2 = 0; i2 < 4; i2++) {
                FMA2(s2[i2][0], av[i2], b0, s2[i2][0]);
                FMA2(s2[i2][1], av[i2], b1, s2[i2][1]);
                FMA2(s2[i2][2], av[i2], b2, s2[i2][2]);
                FMA2(s2[i2][3], av[i2], b3, s2[i2][3]);
            }
        }
        __syncthreads();   // done reading K^T; Xs becomes P^T

        // masks + online softmax + store P^T (row pairs)
        #pragma unroll
        for (int i2 = 0; i2 < 4; i2++) {
            int rA = 2*i2, rB = 2*i2 + 1;
            int giA = i0 + ty*8 + rA;
            u64 mwA = *(const u64*)&Mg[(size_t)giA       * (SEQ/32) + (j0 >> 5)];
            u64 mwB = *(const u64*)&Mg[(size_t)(giA + 1) * (SEQ/32) + (j0 >> 5)];
            u32 nibA = (u32)(mwA >> (4*tx));
            u32 nibB = (u32)(mwB >> (4*tx));

            float2 t0 = unpack2(s2[i2][0]);
            float2 t1 = unpack2(s2[i2][1]);
            float2 t2 = unpack2(s2[i2][2]);
            float2 t3 = unpack2(s2[i2][3]);
            float sA[4] = {t0.x, t1.x, t2.x, t3.x};
            float sB[4] = {t0.y, t1.y, t2.y, t3.y};

            float pA[4], pB[4], corrA, corrB;
            // row A
            {
                #pragma unroll
                for (int j = 0; j < 4; j++)
                    sA[j] = ((nibA >> j) & 1u) ? sA[j] * 0.125f : NEGV;
                float mx = fmaxf(fmaxf(sA[0], sA[1]), fmaxf(sA[2], sA[3]));
                #pragma unroll
                for (int o = 8; o > 0; o >>= 1)
                    mx = fmaxf(mx, __shfl_xor_sync(0xffffffffu, mx, o));
                float mn = fmaxf(m[rA], mx);
                corrA = __expf(m[rA] - mn);
                float rs = 0.f;
                #pragma unroll
                for (int j = 0; j < 4; j++) { pA[j] = __expf(sA[j] - mn); rs += pA[j]; }
                #pragma unroll
                for (int o = 8; o > 0; o >>= 1)
                    rs += __shfl_xor_sync(0xffffffffu, rs, o);
                l[rA] = l[rA]*corrA + rs;
                m[rA] = mn;
            }
            // row B
            {
                #pragma unroll
                for (int j = 0; j < 4; j++)
                    sB[j] = ((nibB >> j) & 1u) ? sB[j] * 0.125f : NEGV;
                float mx = fmaxf(fmaxf(sB[0], sB[1]), fmaxf(sB[2], sB[3]));
                #pragma unroll
                for (int o = 8; o > 0; o >>= 1)
                    mx = fmaxf(mx, __shfl_xor_sync(0xffffffffu, mx, o));
                float mn = fmaxf(m[rB], mx);
                corrB = __expf(m[rB] - mn);
                float rs = 0.f;
                #pragma unroll
                for (int j = 0; j < 4; j++) { pB[j] = __expf(sB[j] - mn); rs += pB[j]; }
                #pragma unroll
                for (int o = 8; o > 0; o >>= 1)
                    rs += __shfl_xor_sync(0xffffffffu, rs, o);
                l[rB] = l[rB]*corrB + rs;
                m[rB] = mn;
            }
            u64 corr2; PACKAB(corr2, corrA, corrB);
            #pragma unroll
            for (int n = 0; n < 4; n++) MUL2(acc[i2][n], acc[i2][n], corr2);

            #pragma unroll
            for (int j = 0; j < 4; j++) {
                u64 pp; PACKAB(pp, pA[j], pB[j]);
                *(u64*)&Xs[PSW(4*tx + j, 8*ty + 2*i2)] = pp;
            }
        }
        __syncthreads();

        // O += P V (p natural i-pairs, v broadcast-packed)
        #pragma unroll 8
        for (int jj = 0; jj < 64; jj++) {
            float4 vv = *(const float4*)&Vs[jj*64 + tx*4];
            u64 v0, v1, v2, v3;
            PACK2(v0, vv.x); PACK2(v1, vv.y); PACK2(v2, vv.z); PACK2(v3, vv.w);
            #pragma unroll
            for (int i2 = 0; i2 < 4; i2++) {
                u64 pp = *(const u64*)&Xs[PSW(jj, 8*ty + 2*i2)];
                FMA2(acc[i2][0], pp, v0, acc[i2][0]);
                FMA2(acc[i2][1], pp, v1, acc[i2][1]);
                FMA2(acc[i2][2], pp, v2, acc[i2][2]);
                FMA2(acc[i2][3], pp, v3, acc[i2][3]);
            }
        }
    }

    float* Og = g_O + (size_t)(b*SEQ + i0)*DIM + h*DK;
    #pragma unroll
    for (int i2 = 0; i2 < 4; i2++) {
        float invA = 1.0f / l[2*i2];
        float invB = 1.0f / l[2*i2 + 1];
        float2 c0 = unpack2(acc[i2][0]);
        float2 c1 = unpack2(acc[i2][1]);
        float2 c2 = unpack2(acc[i2][2]);
        float2 c3 = unpack2(acc[i2][3]);
        size_t r0 = (size_t)(ty*8 + 2*i2) * DIM + tx*4;
        *(float4*)&Og[r0]       = make_float4(c0.x*invA, c1.x*invA, c2.x*invA, c3.x*invA);
        *(float4*)&Og[r0 + DIM] = make_float4(c0.y*invB, c1.y*invB, c2.y*invB, c3.y*invB);
    }
}

// ---------------------------------------------------------------------------
extern "C" void kernel_launch(void* const* d_in, const int* in_sizes, int n_in,
                              void* d_out, int out_size)
{
    const float* x  = (const float*)d_in[0];
    const float* Wq = (const float*)d_in[1];
    const float* Wk = (const float*)d_in[2];
    const float* Wv = (const float*)d_in[3];
    const float* Wo = (const float*)d_in[4];
    const int* seq_mask     = (const int*)d_in[5];
    const int* sparse_masks = (const int*)d_in[6];
    float* out = (float*)d_out;

    mask_prep<<<SEQ/8, 256>>>(seq_mask, sparse_masks);

    dim3 gg(BATCH*SEQ / 64, DIM / 64);             // (64, 8)
    gemm_xwt<<<gg, 128>>>(x, Wq, nullptr, 0, 0);   // -> g_Q
    gemm_xwt<<<gg, 128>>>(x, Wk, nullptr, 0, 1);   // -> g_K
    gemm_xwt<<<gg, 128>>>(x, Wv, nullptr, 0, 2);   // -> g_V

    attn_kernel<<<dim3(SEQ / 64, BATCH * NHEAD), 128>>>();

    gemm_xwt<<<gg, 128>>>(nullptr, Wo, out, 1, 3); // g_O @ Wo^T -> out
    (void)in_sizes; (void)n_in; (void)out_size;
}

// round 4
// speedup vs baseline: 2.5662x; 2.0910x over previous
#include <cuda_runtime.h>
#include <cuda_bf16.h>
#include <math.h>

typedef unsigned int u32;
typedef unsigned long long u64;

#define BATCH 2
#define SEQ   2048
#define DIM   512
#define NHEAD 8
#define DK    64
#define MT    (BATCH*SEQ)
#define LOG2E 1.4426950408889634f

// ---------------- global scratch (alloc-free) ------------------------------
__device__ __nv_bfloat16 gXh[MT*DIM], gXl[MT*DIM];
__device__ __nv_bfloat16 gWh[4][DIM*DIM], gWl[4][DIM*DIM];
__device__ __nv_bfloat16 gQh[MT*DIM], gQl[MT*DIM];   // pre-scaled by 0.125*log2e
__device__ __nv_bfloat16 gKh[MT*DIM], gKl[MT*DIM];
__device__ __nv_bfloat16 gVh[MT*DIM], gVl[MT*DIM];
__device__ __nv_bfloat16 gOh[MT*DIM], gOl[MT*DIM];
__device__ u32 g_mask[4*SEQ*(SEQ/32)];               // [b*2+par][row][word]

// ---------------- helpers ---------------------------------------------------
static __device__ __forceinline__ u32 smem_u32(const void* p) {
    u32 a; asm("{ .reg .u64 t; cvta.to.shared.u64 t, %1; cvt.u32.u64 %0, t; }" : "=r"(a) : "l"(p));
    return a;
}
static __device__ __forceinline__ float ex2f(float x) {
    float y; asm("ex2.approx.f32 %0, %1;" : "=f"(y) : "f"(x)); return y;
}
static __device__ __forceinline__ void split2(float v, __nv_bfloat16& hi, __nv_bfloat16& lo) {
    hi = __float2bfloat16(v);
    lo = __float2bfloat16(v - __bfloat162float(hi));
}
static __device__ __forceinline__ u32 packbf(__nv_bfloat16 a, __nv_bfloat16 b) {
    return (u32)__bfloat16_as_ushort(a) | ((u32)__bfloat16_as_ushort(b) << 16);
}

#define LDM4(r0,r1,r2,r3,a) \
    asm volatile("ldmatrix.sync.aligned.m8n8.x4.shared.b16 {%0,%1,%2,%3}, [%4];" \
        : "=r"(r0),"=r"(r1),"=r"(r2),"=r"(r3) : "r"(a))
#define LDM4T(r0,r1,r2,r3,a) \
    asm volatile("ldmatrix.sync.aligned.m8n8.x4.trans.shared.b16 {%0,%1,%2,%3}, [%4];" \
        : "=r"(r0),"=r"(r1),"=r"(r2),"=r"(r3) : "r"(a))
#define MMA(d,a,b) \
    asm volatile("mma.sync.aligned.m16n8k16.row.col.f32.bf16.bf16.f32 " \
        "{%0,%1,%2,%3}, {%4,%5,%6,%7}, {%8,%9}, {%0,%1,%2,%3};" \
        : "+f"((d)[0]),"+f"((d)[1]),"+f"((d)[2]),"+f"((d)[3]) \
        : "r"((a)[0]),"r"((a)[1]),"r"((a)[2]),"r"((a)[3]),"r"((b)[0]),"r"((b)[1]))

// ---------------- fp32 -> (hi, lo) bf16 split ------------------------------
__global__ void conv_split(const float* __restrict__ src, int sel) {
    __nv_bfloat16 *dh, *dl;
    if (sel == 0) { dh = gXh; dl = gXl; }
    else { dh = gWh[sel-1]; dl = gWl[sel-1]; }
    int i = (blockIdx.x * blockDim.x + threadIdx.x) * 4;
    float4 v = *(const float4*)(src + i);
    __nv_bfloat16 h0,l0,h1,l1,h2,l2,h3,l3;
    split2(v.x,h0,l0); split2(v.y,h1,l1); split2(v.z,h2,l2); split2(v.w,h3,l3);
    *(uint2*)(dh + i) = make_uint2(packbf(h0,h1), packbf(h2,h3));
    *(uint2*)(dl + i) = make_uint2(packbf(l0,l1), packbf(l2,l3));
}

// ---------------- combined masks -> bit tables ------------------------------
__global__ void mask_prep(const int* __restrict__ seq_mask,
                          const int* __restrict__ sparse_masks) {
    int row  = (blockIdx.x * blockDim.x + threadIdx.x) >> 5;
    int lane = threadIdx.x & 31;
    if (row >= SEQ) return;
    const int* s0 = seq_mask     + (size_t)0*SEQ*SEQ + (size_t)row*SEQ;
    const int* s1 = seq_mask     + (size_t)1*SEQ*SEQ + (size_t)row*SEQ;
    const int* p0 = sparse_masks + (size_t)0*SEQ*SEQ + (size_t)row*SEQ;
    const int* p1 = sparse_masks + (size_t)1*SEQ*SEQ + (size_t)row*SEQ;
    for (int w = 0; w < SEQ/32; w++) {
        int j = w*32 + lane;
        int a0 = s0[j], a1 = s1[j], b0 = p0[j], b1 = p1[j];
        u32 m00 = __ballot_sync(0xffffffffu, (a0 & b0) != 0);
        u32 m01 = __ballot_sync(0xffffffffu, (a0 & b1) != 0);
        u32 m10 = __ballot_sync(0xffffffffu, (a1 & b0) != 0);
        u32 m11 = __ballot_sync(0xffffffffu, (a1 & b1) != 0);
        if (lane == 0) {
            g_mask[((size_t)0*SEQ + row)*(SEQ/32) + w] = m00;
            g_mask[((size_t)1*SEQ + row)*(SEQ/32) + w] = m01;
            g_mask[((size_t)2*SEQ + row)*(SEQ/32) + w] = m10;
            g_mask[((size_t)3*SEQ + row)*(SEQ/32) + w] = m11;
        }
    }
}

// ---------------- split-bf16 GEMM: Y = A @ W^T (mma.sync) -------------------
// M=4096, N=512, K=512. Block 128x128, 256 thr (8 warps, 2m x 4n), warp 64x32.
// ysel: 0->Q (scale 0.125*log2e), 1->K, 2->V, 3->fp32 out (A = gO).
__global__ __launch_bounds__(256, 1) void proj_gemm(float* __restrict__ Yout,
                                                    int ysel, int wsel) {
    extern __shared__ char dsm[];
    u32 raw = smem_u32(dsm);
    u32 sb = (raw + 127) & ~127u;
    char* sp = dsm + (sb - raw);

    const __nv_bfloat16* A_h = (ysel == 3) ? gOh : gXh;
    const __nv_bfloat16* A_l = (ysel == 3) ? gOl : gXl;
    const __nv_bfloat16* B_h = gWh[wsel];
    const __nv_bfloat16* B_l = gWl[wsel];

    int tid = threadIdx.x, lane = tid & 31, warp = tid >> 5;
    int t4 = lane & 3, t8 = lane >> 2;
    int mrl = lane & 7, mm = lane >> 3;
    int wm = warp & 1, wn = warp >> 1;
    int m0 = blockIdx.x * 128, n0 = blockIdx.y * 128;

    float C[4][4][4];
    #pragma unroll
    for (int a = 0; a < 4; a++)
        #pragma unroll
        for (int b = 0; b < 4; b++)
            #pragma unroll
            for (int c = 0; c < 4; c++) C[a][b][c] = 0.f;

    for (int k0 = 0; k0 < DIM; k0 += 64) {
        if (k0) __syncthreads();
        #pragma unroll
        for (int q = 0; q < 16; q++) {
            int idx = tid + q*256;
            int mtx = idx >> 10, rem = idx & 1023, r = rem >> 3, ch = rem & 7;
            const __nv_bfloat16* s =
                (mtx == 0 ? A_h : mtx == 1 ? A_l : mtx == 2 ? B_h : B_l)
                + (size_t)((mtx < 2 ? m0 : n0) + r)*DIM + k0 + ch*8;
            *(uint4*)(sp + mtx*16384 + r*128 + ((ch ^ (r & 7)) << 4)) = *(const uint4*)s;
        }
        __syncthreads();

        #pragma unroll
        for (int ks = 0; ks < 4; ks++) {
            u32 AH[4][4], AL[4][4], BH[4][2], BL[4][2];
            int ch = 2*ks + (mm >> 1);
            #pragma unroll
            for (int fm = 0; fm < 4; fm++) {
                int row = wm*64 + fm*16 + (mm & 1)*8 + mrl;
                u32 a = sb + row*128 + ((ch ^ (row & 7)) << 4);
                LDM4(AH[fm][0], AH[fm][1], AH[fm][2], AH[fm][3], a);
                LDM4(AL[fm][0], AL[fm][1], AL[fm][2], AL[fm][3], a + 16384);
            }
            #pragma unroll
            for (int p = 0; p < 2; p++) {
                int row = wn*32 + p*16 + (mm & 1)*8 + mrl;
                u32 a = sb + 32768 + row*128 + ((ch ^ (row & 7)) << 4);
                LDM4(BH[2*p][0], BH[2*p+1][0], BH[2*p][1], BH[2*p+1][1], a);
                LDM4(BL[2*p][0], BL[2*p+1][0], BL[2*p][1], BL[2*p+1][1], a + 16384);
            }
            #pragma unroll
            for (int fm = 0; fm < 4; fm++)
                #pragma unroll
                for (int fn = 0; fn < 4; fn++) {
                    MMA(C[fm][fn], AH[fm], BH[fn]);
                    MMA(C[fm][fn], AH[fm], BL[fn]);
                    MMA(C[fm][fn], AL[fm], BH[fn]);
                }
        }
    }

    float sc = (ysel == 0) ? 0.125f * LOG2E : 1.f;
    #pragma unroll
    for (int fm = 0; fm < 4; fm++) {
        int rA = m0 + wm*64 + fm*16 + t8;
        #pragma unroll
        for (int fn = 0; fn < 4; fn++) {
            int col = n0 + wn*32 + fn*8 + 2*t4;
            float c0 = C[fm][fn][0], c1 = C[fm][fn][1];
            float c2 = C[fm][fn][2], c3 = C[fm][fn][3];
            if (ysel == 3) {
                *(float2*)(Yout + (size_t)rA*DIM + col)     = make_float2(c0, c1);
                *(float2*)(Yout + (size_t)(rA+8)*DIM + col) = make_float2(c2, c3);
            } else {
                c0 *= sc; c1 *= sc; c2 *= sc; c3 *= sc;
                __nv_bfloat16 h0,l0,h1,l1,h2,l2,h3,l3;
                split2(c0,h0,l0); split2(c1,h1,l1); split2(c2,h2,l2); split2(c3,h3,l3);
                __nv_bfloat16* dh = (ysel == 0) ? gQh : (ysel == 1) ? gKh : gVh;
                __nv_bfloat16* dl = (ysel == 0) ? gQl : (ysel == 1) ? gKl : gVl;
                *(u32*)(dh + (size_t)rA*DIM + col)     = packbf(h0, h1);
                *(u32*)(dl + (size_t)rA*DIM + col)     = packbf(l0, l1);
                *(u32*)(dh + (size_t)(rA+8)*DIM + col) = packbf(h2, h3);
                *(u32*)(dl + (size_t)(rA+8)*DIM + col) = packbf(l2, l3);
            }
        }
    }
}

// ---------------- flash attention (mma.sync, FA2 register pipeline) ---------
// CTA: 128 i-rows of one (b,h); 8 warps x 16 rows; j swept in 64-tiles.
// No max-subtraction (logits bounded); masked p = exact 0; O accumulates in
// registers across all j-tiles; single normalize at the end.
__global__ __launch_bounds__(256, 1) void attn_kernel() {
    __shared__ __align__(128) char sK[16384];   // Kh @0, Kl @8192
    __shared__ __align__(128) char sV[16384];   // Vh @0, Vl @8192

    int tid = threadIdx.x, lane = tid & 31, warp = tid >> 5;
    int t4 = lane & 3, t8 = lane >> 2;
    int mrl = lane & 7, mm = lane >> 3;
    int i0 = blockIdx.x * 128;
    int bh = blockIdx.y, b = bh >> 3, hh = bh & 7;
    int combo = b*2 + (hh & 1);

    u32 sKb = smem_u32(sK), sVb = smem_u32(sV);

    // Q fragments (hi/lo) held in registers for the whole kernel
    u32 QA[2][4][4];
    {
        size_t qbase = (size_t)(b*SEQ + i0 + warp*16 + t8)*DIM + hh*DK + 2*t4;
        #pragma unroll
        for (int hl = 0; hl < 2; hl++) {
            const __nv_bfloat16* qp = hl ? gQl : gQh;
            #pragma unroll
            for (int ks = 0; ks < 4; ks++) {
                QA[hl][ks][0] = *(const u32*)(qp + qbase + ks*16);
                QA[hl][ks][1] = *(const u32*)(qp + qbase + ks*16 + 8*DIM);
                QA[hl][ks][2] = *(const u32*)(qp + qbase + ks*16 + 8);
                QA[hl][ks][3] = *(const u32*)(qp + qbase + ks*16 + 8*DIM + 8);
            }
        }
    }

    const u32* mrowA = g_mask + ((size_t)combo*SEQ + i0 + warp*16 + t8)*(SEQ/32);
    const u32* mrowB = mrowA + 8*(SEQ/32);

    float O[8][4];
    #pragma unroll
    for (int f = 0; f < 8; f++)
        #pragma unroll
        for (int c = 0; c < 4; c++) O[f][c] = 0.f;
    float lsA = 0.f, lsB = 0.f;

    const __nv_bfloat16* kvsrc[4];
    kvsrc[0] = gKh; kvsrc[1] = gKl; kvsrc[2] = gVh; kvsrc[3] = gVl;

    for (int j0 = 0; j0 < SEQ; j0 += 64) {
        // cooperative K/V tile load (64 rows x 64 halves x 4 matrices)
        #pragma unroll
        for (int q = 0; q < 8; q++) {
            int idx = tid + q*256;
            int mtx = idx >> 9, rem = idx & 511, r = rem >> 3, ch = rem & 7;
            const __nv_bfloat16* s = kvsrc[mtx] + (size_t)(b*SEQ + j0 + r)*DIM + hh*DK + ch*8;
            char* d = (mtx < 2 ? sK : sV) + (mtx & 1)*8192;
            *(uint4*)(d + r*128 + ((ch ^ (r & 7)) << 4)) = *(const uint4*)s;
        }
        __syncthreads();

        // S = Q K^T  (3 split groups)
        float S[8][4];
        #pragma unroll
        for (int f = 0; f < 8; f++)
            #pragma unroll
            for (int c = 0; c < 4; c++) S[f][c] = 0.f;

        #pragma unroll
        for (int ks = 0; ks < 4; ks++) {
            u32 BH[8][2], BL[8][2];
            int ch = 2*ks + (mm >> 1);
            #pragma unroll
            for (int p = 0; p < 4; p++) {
                int row = 16*p + (mm & 1)*8 + mrl;
                u32 a = sKb + row*128 + ((ch ^ (row & 7)) << 4);
                LDM4(BH[2*p][0], BH[2*p+1][0], BH[2*p][1], BH[2*p+1][1], a);
                LDM4(BL[2*p][0], BL[2*p+1][0], BL[2*p][1], BL[2*p+1][1], a + 8192);
            }
            #pragma unroll
            for (int f = 0; f < 8; f++) {
                MMA(S[f], QA[0][ks], BH[f]);
                MMA(S[f], QA[0][ks], BL[f]);
                MMA(S[f], QA[1][ks], BH[f]);
            }
        }

        // mask + exp (ex2) + split P into A-fragments (registers only)
        uint2 wA = *(const uint2*)(mrowA + (j0 >> 5));
        uint2 wB = *(const uint2*)(mrowB + (j0 >> 5));
        u64 mwA = (u64)wA.x | ((u64)wA.y << 32);
        u64 mwB = (u64)wB.x | ((u64)wB.y << 32);

        u32 PH[4][4], PL[4][4];
        #pragma unroll
        for (int f = 0; f < 8; f++) {
            int sh = 8*f + 2*t4;
            u32 bA = (u32)(mwA >> sh);
            u32 bB = (u32)(mwB >> sh);
            float p0 = (bA & 1u) ? ex2f(S[f][0]) : 0.f;
            float p1 = (bA & 2u) ? ex2f(S[f][1]) : 0.f;
            float p2 = (bB & 1u) ? ex2f(S[f][2]) : 0.f;
            float p3 = (bB & 2u) ? ex2f(S[f][3]) : 0.f;
            lsA += p0 + p1;
            lsB += p2 + p3;
            __nv_bfloat16 h0,l0,h1,l1,h2,l2,h3,l3;
            split2(p0,h0,l0); split2(p1,h1,l1); split2(p2,h2,l2); split2(p3,h3,l3);
            int ks = f >> 1, o = (f & 1)*2;
            PH[ks][o]   = packbf(h0, h1);  PL[ks][o]   = packbf(l0, l1);
            PH[ks][o+1] = packbf(h2, h3);  PL[ks][o+1] = packbf(l2, l3);
        }

        // O += P V  (3 split groups), V fragments via ldmatrix.trans
        #pragma unroll
        for (int ks = 0; ks < 4; ks++) {
            u32 VH[8][2], VL[8][2];
            int row = 16*ks + (mm >> 1)*8 + mrl;
            #pragma unroll
            for (int p = 0; p < 4; p++) {
                int ch = 2*p + (mm & 1);
                u32 a = sVb + row*128 + ((ch ^ (row & 7)) << 4);
                LDM4T(VH[2*p][0], VH[2*p+1][0], VH[2*p][1], VH[2*p+1][1], a);
                LDM4T(VL[2*p][0], VL[2*p+1][0], VL[2*p][1], VL[2*p+1][1], a + 8192);
            }
            #pragma unroll
            for (int f = 0; f < 8; f++) {
                MMA(O[f], PH[ks], VH[f]);
                MMA(O[f], PH[ks], VL[f]);
                MMA(O[f], PL[ks], VH[f]);
            }
        }
        __syncthreads();
    }

    // row-sum reduce across the 4 lanes sharing each row, normalize, store
    lsA += __shfl_xor_sync(0xffffffffu, lsA, 1);
    lsA += __shfl_xor_sync(0xffffffffu, lsA, 2);
    lsB += __shfl_xor_sync(0xffffffffu, lsB, 1);
    lsB += __shfl_xor_sync(0xffffffffu, lsB, 2);
    float invA = (lsA > 0.f) ? 1.0f / lsA : 0.f;
    float invB = (lsB > 0.f) ? 1.0f / lsB : 0.f;

    size_t obase = (size_t)(b*SEQ + i0 + warp*16 + t8)*DIM + hh*DK + 2*t4;
    #pragma unroll
    for (int f = 0; f < 8; f++) {
        float o0 = O[f][0]*invA, o1 = O[f][1]*invA;
        float o2 = O[f][2]*invB, o3 = O[f][3]*invB;
        __nv_bfloat16 h0,l0,h1,l1,h2,l2,h3,l3;
        split2(o0,h0,l0); split2(o1,h1,l1); split2(o2,h2,l2); split2(o3,h3,l3);
        *(u32*)(gOh + obase + 8*f)         = packbf(h0, h1);
        *(u32*)(gOl + obase + 8*f)         = packbf(l0, l1);
        *(u32*)(gOh + obase + 8*f + 8*DIM) = packbf(h2, h3);
        *(u32*)(gOl + obase + 8*f + 8*DIM) = packbf(l2, l3);
    }
}

// ---------------------------------------------------------------------------
extern "C" void kernel_launch(void* const* d_in, const int* in_sizes, int n_in,
                              void* d_out, int out_size)
{
    const float* x  = (const float*)d_in[0];
    const float* Wq = (const float*)d_in[1];
    const float* Wk = (const float*)d_in[2];
    const float* Wv = (const float*)d_in[3];
    const float* Wo = (const float*)d_in[4];
    const int* seq_mask     = (const int*)d_in[5];
    const int* sparse_masks = (const int*)d_in[6];
    float* out = (float*)d_out;

    cudaFuncSetAttribute(proj_gemm, cudaFuncAttributeMaxDynamicSharedMemorySize, 65536);

    mask_prep<<<SEQ/8, 256>>>(seq_mask, sparse_masks);
    conv_split<<<MT*DIM/1024, 256>>>(x, 0);
    conv_split<<<DIM*DIM/1024, 256>>>(Wq, 1);
    conv_split<<<DIM*DIM/1024, 256>>>(Wk, 2);
    conv_split<<<DIM*DIM/1024, 256>>>(Wv, 3);
    conv_split<<<DIM*DIM/1024, 256>>>(Wo, 4);

    dim3 pg(MT/128, DIM/128);                         // (32, 4)
    proj_gemm<<<pg, 256, 65536>>>(nullptr, 0, 0);     // Q (scaled 0.125*log2e)
    proj_gemm<<<pg, 256, 65536>>>(nullptr, 1, 1);     // K
    proj_gemm<<<pg, 256, 65536>>>(nullptr, 2, 2);     // V
    attn_kernel<<<dim3(SEQ/128, BATCH*NHEAD), 256>>>();
    proj_gemm<<<pg, 256, 65536>>>(out, 3, 3);         // O @ Wo^T -> fp32
    (void)in_sizes; (void)n_in; (void)out_size;
}

// round 5
// speedup vs baseline: 3.4405x; 1.3407x over previous
#include <cuda_runtime.h>
#include <cuda_bf16.h>
#include <cuda_fp16.h>
#include <math.h>

typedef unsigned int u32;
typedef unsigned long long u64;

#define BATCH 2
#define SEQ   2048
#define DIM   512
#define NHEAD 8
#define DK    64
#define MT    (BATCH*SEQ)
#define LOG2E 1.4426950408889634f

// ---------------- global scratch (alloc-free) ------------------------------
__device__ __nv_bfloat16 gXh[MT*DIM], gXl[MT*DIM];
__device__ __nv_bfloat16 gWh[4][DIM*DIM], gWl[4][DIM*DIM];
__device__ __half gQ [MT*DIM];                       // pre-scaled 0.125*log2e
__device__ __half gKh[MT*DIM], gKl[MT*DIM];
__device__ __half gVh[MT*DIM], gVl[MT*DIM];
__device__ __nv_bfloat16 gOh[MT*DIM], gOl[MT*DIM];
__device__ u32 g_mask[4*SEQ*(SEQ/32)];               // [b*2+par][row][word]

// ---------------- helpers ---------------------------------------------------
static __device__ __forceinline__ u32 smem_u32(const void* p) {
    u32 a; asm("{ .reg .u64 t; cvta.to.shared.u64 t, %1; cvt.u32.u64 %0, t; }" : "=r"(a) : "l"(p));
    return a;
}
static __device__ __forceinline__ float ex2f(float x) {
    float y; asm("ex2.approx.f32 %0, %1;" : "=f"(y) : "f"(x)); return y;
}
static __device__ __forceinline__ void split2(float v, __nv_bfloat16& hi, __nv_bfloat16& lo) {
    hi = __float2bfloat16(v);
    lo = __float2bfloat16(v - __bfloat162float(hi));
}
static __device__ __forceinline__ u32 packbf(__nv_bfloat16 a, __nv_bfloat16 b) {
    return (u32)__bfloat16_as_ushort(a) | ((u32)__bfloat16_as_ushort(b) << 16);
}
static __device__ __forceinline__ void splith(float v, __half& hi, __half& lo) {
    hi = __float2half_rn(v);
    lo = __float2half_rn(v - __half2float(hi));
}
static __device__ __forceinline__ u32 packh(__half a, __half b) {
    return (u32)__half_as_ushort(a) | ((u32)__half_as_ushort(b) << 16);
}
// packs {lo, hi} halves
static __device__ __forceinline__ u32 cvtf16x2(float lo, float hi) {
    u32 d; asm("cvt.rn.f16x2.f32 %0, %1, %2;" : "=r"(d) : "f"(hi), "f"(lo)); return d;
}

#define LDM4(r0,r1,r2,r3,a) \
    asm volatile("ldmatrix.sync.aligned.m8n8.x4.shared.b16 {%0,%1,%2,%3}, [%4];" \
        : "=r"(r0),"=r"(r1),"=r"(r2),"=r"(r3) : "r"(a))
#define LDM4T(r0,r1,r2,r3,a) \
    asm volatile("ldmatrix.sync.aligned.m8n8.x4.trans.shared.b16 {%0,%1,%2,%3}, [%4];" \
        : "=r"(r0),"=r"(r1),"=r"(r2),"=r"(r3) : "r"(a))
#define MMAB(d,a,b) \
    asm volatile("mma.sync.aligned.m16n8k16.row.col.f32.bf16.bf16.f32 " \
        "{%0,%1,%2,%3}, {%4,%5,%6,%7}, {%8,%9}, {%0,%1,%2,%3};" \
        : "+f"((d)[0]),"+f"((d)[1]),"+f"((d)[2]),"+f"((d)[3]) \
        : "r"((a)[0]),"r"((a)[1]),"r"((a)[2]),"r"((a)[3]),"r"((b)[0]),"r"((b)[1]))
#define MMAH(d,a,b) \
    asm volatile("mma.sync.aligned.m16n8k16.row.col.f32.f16.f16.f32 " \
        "{%0,%1,%2,%3}, {%4,%5,%6,%7}, {%8,%9}, {%0,%1,%2,%3};" \
        : "+f"((d)[0]),"+f"((d)[1]),"+f"((d)[2]),"+f"((d)[3]) \
        : "r"((a)[0]),"r"((a)[1]),"r"((a)[2]),"r"((a)[3]),"r"((b)[0]),"r"((b)[1]))

#define CPA16(d, s) asm volatile("cp.async.cg.shared.global [%0], [%1], 16;" :: "r"(d), "l"(s) : "memory")
#define CPCOMMIT()  asm volatile("cp.async.commit_group;" ::: "memory")
#define CPWAIT1()   asm volatile("cp.async.wait_group 1;" ::: "memory")
#define CPWAIT0()   asm volatile("cp.async.wait_group 0;" ::: "memory")

// ---------------- fp32 -> (hi, lo) bf16 split ------------------------------
__global__ void conv_split(const float* __restrict__ src, int sel) {
    __nv_bfloat16 *dh, *dl;
    if (sel == 0) { dh = gXh; dl = gXl; }
    else { dh = gWh[sel-1]; dl = gWl[sel-1]; }
    int i = (blockIdx.x * blockDim.x + threadIdx.x) * 4;
    float4 v = *(const float4*)(src + i);
    __nv_bfloat16 h0,l0,h1,l1,h2,l2,h3,l3;
    split2(v.x,h0,l0); split2(v.y,h1,l1); split2(v.z,h2,l2); split2(v.w,h3,l3);
    *(uint2*)(dh + i) = make_uint2(packbf(h0,h1), packbf(h2,h3));
    *(uint2*)(dl + i) = make_uint2(packbf(l0,l1), packbf(l2,l3));
}

// ---------------- combined masks -> bit tables ------------------------------
__global__ void mask_prep(const int* __restrict__ seq_mask,
                          const int* __restrict__ sparse_masks) {
    int row  = (blockIdx.x * blockDim.x + threadIdx.x) >> 5;
    int lane = threadIdx.x & 31;
    if (row >= SEQ) return;
    const int* s0 = seq_mask     + (size_t)0*SEQ*SEQ + (size_t)row*SEQ;
    const int* s1 = seq_mask     + (size_t)1*SEQ*SEQ + (size_t)row*SEQ;
    const int* p0 = sparse_masks + (size_t)0*SEQ*SEQ + (size_t)row*SEQ;
    const int* p1 = sparse_masks + (size_t)1*SEQ*SEQ + (size_t)row*SEQ;
    for (int w = 0; w < SEQ/32; w++) {
        int j = w*32 + lane;
        int a0 = s0[j], a1 = s1[j], b0 = p0[j], b1 = p1[j];
        u32 m00 = __ballot_sync(0xffffffffu, (a0 & b0) != 0);
        u32 m01 = __ballot_sync(0xffffffffu, (a0 & b1) != 0);
        u32 m10 = __ballot_sync(0xffffffffu, (a1 & b0) != 0);
        u32 m11 = __ballot_sync(0xffffffffu, (a1 & b1) != 0);
        if (lane == 0) {
            g_mask[((size_t)0*SEQ + row)*(SEQ/32) + w] = m00;
            g_mask[((size_t)1*SEQ + row)*(SEQ/32) + w] = m01;
            g_mask[((size_t)2*SEQ + row)*(SEQ/32) + w] = m10;
            g_mask[((size_t)3*SEQ + row)*(SEQ/32) + w] = m11;
        }
    }
}

// ---------------- split-bf16 GEMM: Y = A @ W^T (mma.sync, cp.async DB) ------
// M=4096, N=512, K=512. Block 128x128, 256 thr, warp 64x32, k-chunk 64.
// ysel: 0->Q fp16 (scale 0.125*log2e), 1->K fp16 hi/lo, 2->V fp16 hi/lo,
//       3->fp32 out (A = gO bf16 splits).
#define PJ_BUF 65536
__global__ __launch_bounds__(256, 1) void proj_gemm(float* __restrict__ Yout,
                                                    int ysel, int wsel) {
    extern __shared__ char dsm[];
    u32 sb = (smem_u32(dsm) + 127) & ~127u;

    const __nv_bfloat16* A_h = (ysel == 3) ? gOh : gXh;
    const __nv_bfloat16* A_l = (ysel == 3) ? gOl : gXl;
    const __nv_bfloat16* B_h = gWh[wsel];
    const __nv_bfloat16* B_l = gWl[wsel];

    int tid = threadIdx.x, lane = tid & 31, warp = tid >> 5;
    int t4 = lane & 3, t8 = lane >> 2;
    int mrl = lane & 7, mm = lane >> 3;
    int wm = warp & 1, wn = warp >> 1;
    int m0 = blockIdx.x * 128, n0 = blockIdx.y * 128;

    // cp.async issue for k-chunk c into buffer buf
    #define PJ_ISSUE(c, buf) do { \
        _Pragma("unroll") \
        for (int q = 0; q < 16; q++) { \
            int idx = tid + q*256; \
            int mtx = idx >> 10, rem = idx & 1023, r = rem >> 3, ch = rem & 7; \
            const __nv_bfloat16* s = \
                (mtx == 0 ? A_h : mtx == 1 ? A_l : mtx == 2 ? B_h : B_l) \
                + (size_t)((mtx < 2 ? m0 : n0) + r)*DIM + (c)*64 + ch*8; \
            u32 d = sb + (buf)*PJ_BUF + mtx*16384 + r*128 + ((ch ^ (r & 7)) << 4); \
            CPA16(d, s); \
        } \
        CPCOMMIT(); \
    } while (0)

    float C[4][4][4];
    #pragma unroll
    for (int a = 0; a < 4; a++)
        #pragma unroll
        for (int b = 0; b < 4; b++)
            #pragma unroll
            for (int c = 0; c < 4; c++) C[a][b][c] = 0.f;

    PJ_ISSUE(0, 0);
    PJ_ISSUE(1, 1);

    for (int c = 0; c < 8; c++) {
        if (c < 7) CPWAIT1(); else CPWAIT0();
        __syncthreads();
        u32 bb = sb + (c & 1)*PJ_BUF;

        #pragma unroll
        for (int ks = 0; ks < 4; ks++) {
            u32 AH[4][4], AL[4][4], BH[4][2], BL[4][2];
            int ch = 2*ks + (mm >> 1);
            #pragma unroll
            for (int fm = 0; fm < 4; fm++) {
                int row = wm*64 + fm*16 + (mm & 1)*8 + mrl;
                u32 a = bb + row*128 + ((ch ^ (row & 7)) << 4);
                LDM4(AH[fm][0], AH[fm][1], AH[fm][2], AH[fm][3], a);
                LDM4(AL[fm][0], AL[fm][1], AL[fm][2], AL[fm][3], a + 16384);
            }
            #pragma unroll
            for (int p = 0; p < 2; p++) {
                int row = wn*32 + p*16 + (mm & 1)*8 + mrl;
                u32 a = bb + 32768 + row*128 + ((ch ^ (row & 7)) << 4);
                LDM4(BH[2*p][0], BH[2*p+1][0], BH[2*p][1], BH[2*p+1][1], a);
                LDM4(BL[2*p][0], BL[2*p+1][0], BL[2*p][1], BL[2*p+1][1], a + 16384);
            }
            #pragma unroll
            for (int fm = 0; fm < 4; fm++)
                #pragma unroll
                for (int fn = 0; fn < 4; fn++) {
                    MMAB(C[fm][fn], AH[fm], BH[fn]);
                    MMAB(C[fm][fn], AH[fm], BL[fn]);
                    MMAB(C[fm][fn], AL[fm], BH[fn]);
                }
        }
        __syncthreads();
        if (c + 2 < 8) PJ_ISSUE(c + 2, c & 1);
    }

    #pragma unroll
    for (int fm = 0; fm < 4; fm++) {
        int rA = m0 + wm*64 + fm*16 + t8;
        #pragma unroll
        for (int fn = 0; fn < 4; fn++) {
            int col = n0 + wn*32 + fn*8 + 2*t4;
            float c0 = C[fm][fn][0], c1 = C[fm][fn][1];
            float c2 = C[fm][fn][2], c3 = C[fm][fn][3];
            if (ysel == 3) {
                *(float2*)(Yout + (size_t)rA*DIM + col)     = make_float2(c0, c1);
                *(float2*)(Yout + (size_t)(rA+8)*DIM + col) = make_float2(c2, c3);
            } else if (ysel == 0) {
                float sc = 0.125f * LOG2E;
                *(u32*)(gQ + (size_t)rA*DIM + col)     = cvtf16x2(c0*sc, c1*sc);
                *(u32*)(gQ + (size_t)(rA+8)*DIM + col) = cvtf16x2(c2*sc, c3*sc);
            } else {
                __half h0,l0,h1,l1,h2,l2,h3,l3;
                splith(c0,h0,l0); splith(c1,h1,l1); splith(c2,h2,l2); splith(c3,h3,l3);
                __half* dh = (ysel == 1) ? gKh : gVh;
                __half* dl = (ysel == 1) ? gKl : gVl;
                *(u32*)(dh + (size_t)rA*DIM + col)     = packh(h0, h1);
                *(u32*)(dl + (size_t)rA*DIM + col)     = packh(l0, l1);
                *(u32*)(dh + (size_t)(rA+8)*DIM + col) = packh(h2, h3);
                *(u32*)(dl + (size_t)(rA+8)*DIM + col) = packh(l2, l3);
            }
        }
    }
}

// ---------------- flash attention (fp16 mma, cp.async double buffer) --------
// CTA: 128 i-rows of one (b,h); 8 warps x 16 rows; 32 j-tiles of 64.
// S = Q*(KH+KL) [2 groups], O += P*(VH+VL) [2 groups]; P single fp16.
#define AT_BUF 32768
__global__ __launch_bounds__(256, 1) void attn_kernel() {
    extern __shared__ char dsm[];
    u32 sb = (smem_u32(dsm) + 127) & ~127u;

    int tid = threadIdx.x, lane = tid & 31, warp = tid >> 5;
    int t4 = lane & 3, t8 = lane >> 2;
    int mrl = lane & 7, mm = lane >> 3;
    int i0 = blockIdx.x * 128;
    int bh = blockIdx.y, b = bh >> 3, hh = bh & 7;
    int combo = b*2 + (hh & 1);

    const __half* kvsrc[4] = {gKh, gKl, gVh, gVl};

    // issue cp.async for j-tile jt (64 rows) into buffer buf:
    // layout: KH @0, KL @8192, VH @16384, VL @24576 (64 rows x 128B, swizzled)
    #define AT_ISSUE(jt, buf) do { \
        _Pragma("unroll") \
        for (int q = 0; q < 8; q++) { \
            int idx = tid + q*256; \
            int mtx = idx >> 9, rem = idx & 511, r = rem >> 3, ch = rem & 7; \
            const __half* s = kvsrc[mtx] + (size_t)(b*SEQ + (jt)*64 + r)*DIM + hh*DK + ch*8; \
            u32 d = sb + (buf)*AT_BUF + mtx*8192 + r*128 + ((ch ^ (r & 7)) << 4); \
            CPA16(d, s); \
        } \
        CPCOMMIT(); \
    } while (0)

    AT_ISSUE(0, 0);
    AT_ISSUE(1, 1);

    // Q fragments (single fp16) held in registers for the whole kernel
    u32 QA[4][4];
    {
        size_t qbase = (size_t)(b*SEQ + i0 + warp*16 + t8)*DIM + hh*DK + 2*t4;
        #pragma unroll
        for (int ks = 0; ks < 4; ks++) {
            QA[ks][0] = *(const u32*)(gQ + qbase + ks*16);
            QA[ks][1] = *(const u32*)(gQ + qbase + ks*16 + 8*DIM);
            QA[ks][2] = *(const u32*)(gQ + qbase + ks*16 + 8);
            QA[ks][3] = *(const u32*)(gQ + qbase + ks*16 + 8*DIM + 8);
        }
    }

    const u32* mrowA = g_mask + ((size_t)combo*SEQ + i0 + warp*16 + t8)*(SEQ/32);
    const u32* mrowB = mrowA + 8*(SEQ/32);

    float O[8][4];
    #pragma unroll
    for (int f = 0; f < 8; f++)
        #pragma unroll
        for (int c = 0; c < 4; c++) O[f][c] = 0.f;
    float lsA = 0.f, lsB = 0.f;

    for (int t = 0; t < 32; t++) {
        if (t < 31) CPWAIT1(); else CPWAIT0();
        __syncthreads();
        u32 kb = sb + (t & 1)*AT_BUF;
        u32 vb = kb + 16384;

        // S = Q K^T  (2 groups)
        float S[8][4];
        #pragma unroll
        for (int f = 0; f < 8; f++)
            #pragma unroll
            for (int c = 0; c < 4; c++) S[f][c] = 0.f;

        #pragma unroll
        for (int ks = 0; ks < 4; ks++) {
            u32 BH[8][2], BL[8][2];
            int ch = 2*ks + (mm >> 1);
            #pragma unroll
            for (int p = 0; p < 4; p++) {
                int row = 16*p + (mm & 1)*8 + mrl;
                u32 a = kb + row*128 + ((ch ^ (row & 7)) << 4);
                LDM4(BH[2*p][0], BH[2*p+1][0], BH[2*p][1], BH[2*p+1][1], a);
                LDM4(BL[2*p][0], BL[2*p+1][0], BL[2*p][1], BL[2*p+1][1], a + 8192);
            }
            #pragma unroll
            for (int f = 0; f < 8; f++) {
                MMAH(S[f], QA[ks], BH[f]);
                MMAH(S[f], QA[ks], BL[f]);
            }
        }

        // mask + ex2 + pack P to fp16 A-fragments (registers only)
        uint2 wA = *(const uint2*)(mrowA + (t << 1));
        uint2 wB = *(const uint2*)(mrowB + (t << 1));
        u64 mwA = (u64)wA.x | ((u64)wA.y << 32);
        u64 mwB = (u64)wB.x | ((u64)wB.y << 32);

        u32 PH[4][4];
        #pragma unroll
        for (int f = 0; f < 8; f++) {
            int sh = 8*f + 2*t4;
            u32 bA = (u32)(mwA >> sh);
            u32 bB = (u32)(mwB >> sh);
            float p0 = (bA & 1u) ? ex2f(S[f][0]) : 0.f;
            float p1 = (bA & 2u) ? ex2f(S[f][1]) : 0.f;
            float p2 = (bB & 1u) ? ex2f(S[f][2]) : 0.f;
            float p3 = (bB & 2u) ? ex2f(S[f][3]) : 0.f;
            lsA += p0 + p1;
            lsB += p2 + p3;
            int ks = f >> 1, o = (f & 1)*2;
            PH[ks][o]   = cvtf16x2(p0, p1);
            PH[ks][o+1] = cvtf16x2(p2, p3);
        }

        // O += P V  (2 groups), V fragments via ldmatrix.trans
        #pragma unroll
        for (int ks = 0; ks < 4; ks++) {
            u32 VH[8][2], VL[8][2];
            int row = 16*ks + (mm >> 1)*8 + mrl;
            #pragma unroll
            for (int p = 0; p < 4; p++) {
                int ch = 2*p + (mm & 1);
                u32 a = vb + row*128 + ((ch ^ (row & 7)) << 4);
                LDM4T(VH[2*p][0], VH[2*p+1][0], VH[2*p][1], VH[2*p+1][1], a);
                LDM4T(VL[2*p][0], VL[2*p+1][0], VL[2*p][1], VL[2*p+1][1], a + 8192);
            }
            #pragma unroll
            for (int f = 0; f < 8; f++) {
                MMAH(O[f], PH[ks], VH[f]);
                MMAH(O[f], PH[ks], VL[f]);
            }
        }
        __syncthreads();
        if (t + 2 < 32) AT_ISSUE(t + 2, t & 1);
    }

    // row-sum reduce across the 4 lanes sharing each row, normalize, store
    lsA += __shfl_xor_sync(0xffffffffu, lsA, 1);
    lsA += __shfl_xor_sync(0xffffffffu, lsA, 2);
    lsB += __shfl_xor_sync(0xffffffffu, lsB, 1);
    lsB += __shfl_xor_sync(0xffffffffu, lsB, 2);
    float invA = (lsA > 0.f) ? 1.0f / lsA : 0.f;
    float invB = (lsB > 0.f) ? 1.0f / lsB : 0.f;

    size_t obase = (size_t)(b*SEQ + i0 + warp*16 + t8)*DIM + hh*DK + 2*t4;
    #pragma unroll
    for (int f = 0; f < 8; f++) {
        float o0 = O[f][0]*invA, o1 = O[f][1]*invA;
        float o2 = O[f][2]*invB, o3 = O[f][3]*invB;
        __nv_bfloat16 h0,l0,h1,l1,h2,l2,h3,l3;
        split2(o0,h0,l0); split2(o1,h1,l1); split2(o2,h2,l2); split2(o3,h3,l3);
        *(u32*)(gOh + obase + 8*f)         = packbf(h0, h1);
        *(u32*)(gOl + obase + 8*f)         = packbf(l0, l1);
        *(u32*)(gOh + obase + 8*f + 8*DIM) = packbf(h2, h3);
        *(u32*)(gOl + obase + 8*f + 8*DIM) = packbf(l2, l3);
    }
}

// ---------------------------------------------------------------------------
extern "C" void kernel_launch(void* const* d_in, const int* in_sizes, int n_in,
                              void* d_out, int out_size)
{
    const float* x  = (const float*)d_in[0];
    const float* Wq = (const float*)d_in[1];
    const float* Wk = (const float*)d_in[2];
    const float* Wv = (const float*)d_in[3];
    const float* Wo = (const float*)d_in[4];
    const int* seq_mask     = (const int*)d_in[5];
    const int* sparse_masks = (const int*)d_in[6];
    float* out = (float*)d_out;

    cudaFuncSetAttribute(proj_gemm,   cudaFuncAttributeMaxDynamicSharedMemorySize, 2*PJ_BUF);
    cudaFuncSetAttribute(attn_kernel, cudaFuncAttributeMaxDynamicSharedMemorySize, 2*AT_BUF);

    mask_prep<<<SEQ/8, 256>>>(seq_mask, sparse_masks);
    conv_split<<<MT*DIM/1024, 256>>>(x, 0);
    conv_split<<<DIM*DIM/1024, 256>>>(Wq, 1);
    conv_split<<<DIM*DIM/1024, 256>>>(Wk, 2);
    conv_split<<<DIM*DIM/1024, 256>>>(Wv, 3);
    conv_split<<<DIM*DIM/1024, 256>>>(Wo, 4);

    dim3 pg(MT/128, DIM/128);                           // (32, 4)
    proj_gemm<<<pg, 256, 2*PJ_BUF>>>(nullptr, 0, 0);    // Q fp16 (scaled)
    proj_gemm<<<pg, 256, 2*PJ_BUF>>>(nullptr, 1, 1);    // K fp16 hi/lo
    proj_gemm<<<pg, 256, 2*PJ_BUF>>>(nullptr, 2, 2);    // V fp16 hi/lo
    attn_kernel<<<dim3(SEQ/128, BATCH*NHEAD), 256, 2*AT_BUF>>>();
    proj_gemm<<<pg, 256, 2*PJ_BUF>>>(out, 3, 3);        // O @ Wo^T -> fp32
    (void)in_sizes; (void)n_in; (void)out_size;
}

// round 6
// speedup vs baseline: 4.6423x; 1.3493x over previous
#include <cuda_runtime.h>
#include <cuda_bf16.h>
#include <cuda_fp16.h>
#include <math.h>

typedef unsigned int u32;
typedef unsigned long long u64;

#define BATCH 2
#define SEQ   2048
#define DIM   512
#define NHEAD 8
#define DK    64
#define MT    (BATCH*SEQ)
#define LOG2E 1.4426950408889634f

// ---------------- global scratch (alloc-free) ------------------------------
__device__ __nv_bfloat16 gXh[MT*DIM], gXl[MT*DIM];
__device__ __nv_bfloat16 gWh[4][DIM*DIM], gWl[4][DIM*DIM];  // 0..2 = QKV (contig), 3 = O
__device__ __half gQ[MT*DIM];                // pre-scaled 0.125*log2e
__device__ __half gK[MT*DIM];
__device__ __half gV[MT*DIM];
__device__ __nv_bfloat16 gOh[MT*DIM], gOl[MT*DIM];
__device__ u32 g_mask[4*SEQ*(SEQ/32)];       // [b*2+par][row][word]

// ---------------- helpers ---------------------------------------------------
static __device__ __forceinline__ u32 smem_u32(const void* p) {
    u32 a; asm("{ .reg .u64 t; cvta.to.shared.u64 t, %1; cvt.u32.u64 %0, t; }" : "=r"(a) : "l"(p));
    return a;
}
static __device__ __forceinline__ float ex2f(float x) {
    float y; asm("ex2.approx.f32 %0, %1;" : "=f"(y) : "f"(x)); return y;
}
static __device__ __forceinline__ void split2(float v, __nv_bfloat16& hi, __nv_bfloat16& lo) {
    hi = __float2bfloat16(v);
    lo = __float2bfloat16(v - __bfloat162float(hi));
}
static __device__ __forceinline__ u32 packbf(__nv_bfloat16 a, __nv_bfloat16 b) {
    return (u32)__bfloat16_as_ushort(a) | ((u32)__bfloat16_as_ushort(b) << 16);
}
// packs {lo, hi} halves
static __device__ __forceinline__ u32 cvtf16x2(float lo, float hi) {
    u32 d; asm("cvt.rn.f16x2.f32 %0, %1, %2;" : "=r"(d) : "f"(hi), "f"(lo)); return d;
}

#define LDM4(r0,r1,r2,r3,a) \
    asm volatile("ldmatrix.sync.aligned.m8n8.x4.shared.b16 {%0,%1,%2,%3}, [%4];" \
        : "=r"(r0),"=r"(r1),"=r"(r2),"=r"(r3) : "r"(a))
#define LDM4T(r0,r1,r2,r3,a) \
    asm volatile("ldmatrix.sync.aligned.m8n8.x4.trans.shared.b16 {%0,%1,%2,%3}, [%4];" \
        : "=r"(r0),"=r"(r1),"=r"(r2),"=r"(r3) : "r"(a))
#define MMAB(d,a,b) \
    asm volatile("mma.sync.aligned.m16n8k16.row.col.f32.bf16.bf16.f32 " \
        "{%0,%1,%2,%3}, {%4,%5,%6,%7}, {%8,%9}, {%0,%1,%2,%3};" \
        : "+f"((d)[0]),"+f"((d)[1]),"+f"((d)[2]),"+f"((d)[3]) \
        : "r"((a)[0]),"r"((a)[1]),"r"((a)[2]),"r"((a)[3]),"r"((b)[0]),"r"((b)[1]))
#define MMAH(d,a,b) \
    asm volatile("mma.sync.aligned.m16n8k16.row.col.f32.f16.f16.f32 " \
        "{%0,%1,%2,%3}, {%4,%5,%6,%7}, {%8,%9}, {%0,%1,%2,%3};" \
        : "+f"((d)[0]),"+f"((d)[1]),"+f"((d)[2]),"+f"((d)[3]) \
        : "r"((a)[0]),"r"((a)[1]),"r"((a)[2]),"r"((a)[3]),"r"((b)[0]),"r"((b)[1]))

#define CPA16(d, s) asm volatile("cp.async.cg.shared.global [%0], [%1], 16;" :: "r"(d), "l"(s) : "memory")
#define CPCOMMIT()  asm volatile("cp.async.commit_group;" ::: "memory")
#define CPWAIT(n)   asm volatile("cp.async.wait_group %0;" :: "n"(n) : "memory")

// ---------------- fp32 -> (hi, lo) bf16 split: x ----------------------------
__global__ void conv_x(const float* __restrict__ src) {
    int i = (blockIdx.x * blockDim.x + threadIdx.x) * 4;
    float4 v = *(const float4*)(src + i);
    __nv_bfloat16 h0,l0,h1,l1,h2,l2,h3,l3;
    split2(v.x,h0,l0); split2(v.y,h1,l1); split2(v.z,h2,l2); split2(v.w,h3,l3);
    *(uint2*)(gXh + i) = make_uint2(packbf(h0,h1), packbf(h2,h3));
    *(uint2*)(gXl + i) = make_uint2(packbf(l0,l1), packbf(l2,l3));
}

// ---------------- fp32 -> (hi, lo) bf16 split: all 4 weights ----------------
__global__ void conv_w(const float* __restrict__ Wq, const float* __restrict__ Wk,
                       const float* __restrict__ Wv, const float* __restrict__ Wo) {
    int sel = blockIdx.x >> 8;               // 256 blocks per weight
    int blk = blockIdx.x & 255;
    const float* src = sel == 0 ? Wq : sel == 1 ? Wk : sel == 2 ? Wv : Wo;
    int i = (blk * blockDim.x + threadIdx.x) * 4;
    float4 v = *(const float4*)(src + i);
    __nv_bfloat16 h0,l0,h1,l1,h2,l2,h3,l3;
    split2(v.x,h0,l0); split2(v.y,h1,l1); split2(v.z,h2,l2); split2(v.w,h3,l3);
    *(uint2*)(gWh[sel] + i) = make_uint2(packbf(h0,h1), packbf(h2,h3));
    *(uint2*)(gWl[sel] + i) = make_uint2(packbf(l0,l1), packbf(l2,l3));
}

// ---------------- combined masks -> bit tables ------------------------------
__global__ void mask_prep(const int* __restrict__ seq_mask,
                          const int* __restrict__ sparse_masks) {
    int row  = (blockIdx.x * blockDim.x + threadIdx.x) >> 5;
    int lane = threadIdx.x & 31;
    if (row >= SEQ) return;
    const int* s0 = seq_mask     + (size_t)0*SEQ*SEQ + (size_t)row*SEQ;
    const int* s1 = seq_mask     + (size_t)1*SEQ*SEQ + (size_t)row*SEQ;
    const int* p0 = sparse_masks + (size_t)0*SEQ*SEQ + (size_t)row*SEQ;
    const int* p1 = sparse_masks + (size_t)1*SEQ*SEQ + (size_t)row*SEQ;
    for (int w = 0; w < SEQ/32; w++) {
        int j = w*32 + lane;
        int a0 = s0[j], a1 = s1[j], b0 = p0[j], b1 = p1[j];
        u32 m00 = __ballot_sync(0xffffffffu, (a0 & b0) != 0);
        u32 m01 = __ballot_sync(0xffffffffu, (a0 & b1) != 0);
        u32 m10 = __ballot_sync(0xffffffffu, (a1 & b0) != 0);
        u32 m11 = __ballot_sync(0xffffffffu, (a1 & b1) != 0);
        if (lane == 0) {
            g_mask[((size_t)0*SEQ + row)*(SEQ/32) + w] = m00;
            g_mask[((size_t)1*SEQ + row)*(SEQ/32) + w] = m01;
            g_mask[((size_t)2*SEQ + row)*(SEQ/32) + w] = m10;
            g_mask[((size_t)3*SEQ + row)*(SEQ/32) + w] = m11;
        }
    }
}

// ---------------- split-bf16 GEMM (mma.sync, cp.async DB) -------------------
// mode 0: A = x splits, B = QKV concat [1536][512]; epilogue -> gQ/gK/gV fp16.
// mode 1: A = O splits,  B = Wo [512][512];          epilogue -> fp32 out.
#define PJ_BUF 65536
__global__ __launch_bounds__(256, 1) void proj_gemm(float* __restrict__ Yout, int mode) {
    extern __shared__ char dsm[];
    u32 sb = (smem_u32(dsm) + 127) & ~127u;

    const __nv_bfloat16* A_h = mode ? gOh : gXh;
    const __nv_bfloat16* A_l = mode ? gOl : gXl;
    const __nv_bfloat16* B_h = mode ? gWh[3] : gWh[0];
    const __nv_bfloat16* B_l = mode ? gWl[3] : gWl[0];

    int tid = threadIdx.x, lane = tid & 31, warp = tid >> 5;
    int t4 = lane & 3, t8 = lane >> 2;
    int mrl = lane & 7, mm = lane >> 3;
    int wm = warp & 1, wn = warp >> 1;
    int m0 = blockIdx.x * 128, n0 = blockIdx.y * 128;

    #define PJ_ISSUE(c, buf) do { \
        _Pragma("unroll") \
        for (int q = 0; q < 16; q++) { \
            int idx = tid + q*256; \
            int mtx = idx >> 10, rem = idx & 1023, r = rem >> 3, ch = rem & 7; \
            const __nv_bfloat16* s = \
                (mtx == 0 ? A_h : mtx == 1 ? A_l : mtx == 2 ? B_h : B_l) \
                + (size_t)((mtx < 2 ? m0 : n0) + r)*DIM + (c)*64 + ch*8; \
            u32 d = sb + (buf)*PJ_BUF + mtx*16384 + r*128 + ((ch ^ (r & 7)) << 4); \
            CPA16(d, s); \
        } \
        CPCOMMIT(); \
    } while (0)

    float C[4][4][4];
    #pragma unroll
    for (int a = 0; a < 4; a++)
        #pragma unroll
        for (int b = 0; b < 4; b++)
            #pragma unroll
            for (int c = 0; c < 4; c++) C[a][b][c] = 0.f;

    PJ_ISSUE(0, 0);
    PJ_ISSUE(1, 1);

    for (int c = 0; c < 8; c++) {
        if (c < 7) CPWAIT(1); else CPWAIT(0);
        __syncthreads();
        u32 bb = sb + (c & 1)*PJ_BUF;

        #pragma unroll
        for (int ks = 0; ks < 4; ks++) {
            u32 AH[4][4], AL[4][4], BH[4][2], BL[4][2];
            int ch = 2*ks + (mm >> 1);
            #pragma unroll
            for (int fm = 0; fm < 4; fm++) {
                int row = wm*64 + fm*16 + (mm & 1)*8 + mrl;
                u32 a = bb + row*128 + ((ch ^ (row & 7)) << 4);
                LDM4(AH[fm][0], AH[fm][1], AH[fm][2], AH[fm][3], a);
                LDM4(AL[fm][0], AL[fm][1], AL[fm][2], AL[fm][3], a + 16384);
            }
            #pragma unroll
            for (int p = 0; p < 2; p++) {
                int row = wn*32 + p*16 + (mm & 1)*8 + mrl;
                u32 a = bb + 32768 + row*128 + ((ch ^ (row & 7)) << 4);
                LDM4(BH[2*p][0], BH[2*p+1][0], BH[2*p][1], BH[2*p+1][1], a);
                LDM4(BL[2*p][0], BL[2*p+1][0], BL[2*p][1], BL[2*p+1][1], a + 16384);
            }
            #pragma unroll
            for (int fm = 0; fm < 4; fm++)
                #pragma unroll
                for (int fn = 0; fn < 4; fn++) {
                    MMAB(C[fm][fn], AH[fm], BH[fn]);
                    MMAB(C[fm][fn], AH[fm], BL[fn]);
                    MMAB(C[fm][fn], AL[fm], BH[fn]);
                }
        }
        __syncthreads();
        if (c + 2 < 8) PJ_ISSUE(c + 2, c & 1);
    }

    #pragma unroll
    for (int fm = 0; fm < 4; fm++) {
        int rA = m0 + wm*64 + fm*16 + t8;
        #pragma unroll
        for (int fn = 0; fn < 4; fn++) {
            int n = n0 + wn*32 + fn*8 + 2*t4;
            float c0 = C[fm][fn][0], c1 = C[fm][fn][1];
            float c2 = C[fm][fn][2], c3 = C[fm][fn][3];
            if (mode) {
                *(float2*)(Yout + (size_t)rA*DIM + n)     = make_float2(c0, c1);
                *(float2*)(Yout + (size_t)(rA+8)*DIM + n) = make_float2(c2, c3);
            } else {
                int osel = n >> 9, col = n & 511;
                __half* dst = osel == 0 ? gQ : osel == 1 ? gK : gV;
                float sc = osel == 0 ? 0.125f * LOG2E : 1.f;
                *(u32*)(dst + (size_t)rA*DIM + col)     = cvtf16x2(c0*sc, c1*sc);
                *(u32*)(dst + (size_t)(rA+8)*DIM + col) = cvtf16x2(c2*sc, c3*sc);
            }
        }
    }
}

// ---------------- flash attention (fp16 mma, 3-stage cp.async) --------------
// CTA: 128 i-rows of one (b,h); 8 warps x 16 rows; 32 j-tiles of 64.
// Single-fp16 K and V: S = Q K^T (1 group), O += P V (1 group).
#define AT_STG 16384   // per stage: K 8KB @0, V 8KB @8192
__global__ __launch_bounds__(256, 2) void attn_kernel() {
    extern __shared__ char dsm[];
    u32 sb = (smem_u32(dsm) + 127) & ~127u;

    int tid = threadIdx.x, lane = tid & 31, warp = tid >> 5;
    int t4 = lane & 3, t8 = lane >> 2;
    int mrl = lane & 7, mm = lane >> 3;
    int i0 = blockIdx.x * 128;
    int bh = blockIdx.y, b = bh >> 3, hh = bh & 7;
    int combo = b*2 + (hh & 1);

    #define AT_ISSUE(jt, st) do { \
        _Pragma("unroll") \
        for (int q = 0; q < 4; q++) { \
            int idx = tid + q*256; \
            int mtx = idx >> 9, rem = idx & 511, r = rem >> 3, ch = rem & 7; \
            const __half* s = (mtx ? gV : gK) + (size_t)(b*SEQ + (jt)*64 + r)*DIM + hh*DK + ch*8; \
            u32 d = sb + (st)*AT_STG + mtx*8192 + r*128 + ((ch ^ (r & 7)) << 4); \
            CPA16(d, s); \
        } \
        CPCOMMIT(); \
    } while (0)

    AT_ISSUE(0, 0);
    AT_ISSUE(1, 1);
    AT_ISSUE(2, 2);

    // Q fragments (fp16) held in registers for the whole kernel
    u32 QA[4][4];
    {
        size_t qbase = (size_t)(b*SEQ + i0 + warp*16 + t8)*DIM + hh*DK + 2*t4;
        #pragma unroll
        for (int ks = 0; ks < 4; ks++) {
            QA[ks][0] = *(const u32*)(gQ + qbase + ks*16);
            QA[ks][1] = *(const u32*)(gQ + qbase + ks*16 + 8*DIM);
            QA[ks][2] = *(const u32*)(gQ + qbase + ks*16 + 8);
            QA[ks][3] = *(const u32*)(gQ + qbase + ks*16 + 8*DIM + 8);
        }
    }

    const u32* mrowA = g_mask + ((size_t)combo*SEQ + i0 + warp*16 + t8)*(SEQ/32);
    const u32* mrowB = mrowA + 8*(SEQ/32);

    float O[8][4];
    #pragma unroll
    for (int f = 0; f < 8; f++)
        #pragma unroll
        for (int c = 0; c < 4; c++) O[f][c] = 0.f;
    float lsA = 0.f, lsB = 0.f;

    int stage = 0;
    for (int t = 0; t < 32; t++) {
        if (t <= 29) CPWAIT(2); else if (t == 30) CPWAIT(1); else CPWAIT(0);
        __syncthreads();
        u32 kb = sb + stage*AT_STG;
        u32 vb = kb + 8192;

        // S = Q K^T
        float S[8][4];
        #pragma unroll
        for (int f = 0; f < 8; f++)
            #pragma unroll
            for (int c = 0; c < 4; c++) S[f][c] = 0.f;

        #pragma unroll
        for (int ks = 0; ks < 4; ks++) {
            u32 BH[8][2];
            int ch = 2*ks + (mm >> 1);
            #pragma unroll
            for (int p = 0; p < 4; p++) {
                int row = 16*p + (mm & 1)*8 + mrl;
                u32 a = kb + row*128 + ((ch ^ (row & 7)) << 4);
                LDM4(BH[2*p][0], BH[2*p+1][0], BH[2*p][1], BH[2*p+1][1], a);
            }
            #pragma unroll
            for (int f = 0; f < 8; f++) MMAH(S[f], QA[ks], BH[f]);
        }

        // mask + ex2 + pack P to fp16 A-fragments (registers only)
        uint2 wA = *(const uint2*)(mrowA + (t << 1));
        uint2 wB = *(const uint2*)(mrowB + (t << 1));
        u64 mwA = (u64)wA.x | ((u64)wA.y << 32);
        u64 mwB = (u64)wB.x | ((u64)wB.y << 32);

        u32 PH[4][4];
        #pragma unroll
        for (int f = 0; f < 8; f++) {
            int sh = 8*f + 2*t4;
            u32 bA = (u32)(mwA >> sh);
            u32 bB = (u32)(mwB >> sh);
            float p0 = (bA & 1u) ? ex2f(S[f][0]) : 0.f;
            float p1 = (bA & 2u) ? ex2f(S[f][1]) : 0.f;
            float p2 = (bB & 1u) ? ex2f(S[f][2]) : 0.f;
            float p3 = (bB & 2u) ? ex2f(S[f][3]) : 0.f;
            lsA += p0 + p1;
            lsB += p2 + p3;
            int ks = f >> 1, o = (f & 1)*2;
            PH[ks][o]   = cvtf16x2(p0, p1);
            PH[ks][o+1] = cvtf16x2(p2, p3);
        }

        // O += P V  (V fragments via ldmatrix.trans)
        #pragma unroll
        for (int ks = 0; ks < 4; ks++) {
            u32 VH[8][2];
            int row = 16*ks + (mm >> 1)*8 + mrl;
            #pragma unroll
            for (int p = 0; p < 4; p++) {
                int ch = 2*p + (mm & 1);
                u32 a = vb + row*128 + ((ch ^ (row & 7)) << 4);
                LDM4T(VH[2*p][0], VH[2*p+1][0], VH[2*p][1], VH[2*p+1][1], a);
            }
            #pragma unroll
            for (int f = 0; f < 8; f++) MMAH(O[f], PH[ks], VH[f]);
        }
        __syncthreads();
        if (t + 3 < 32) AT_ISSUE(t + 3, stage);
        stage = (stage == 2) ? 0 : stage + 1;
    }

    // reduce row sums across the 4 lanes sharing each row, normalize, store
    lsA += __shfl_xor_sync(0xffffffffu, lsA, 1);
    lsA += __shfl_xor_sync(0xffffffffu, lsA, 2);
    lsB += __shfl_xor_sync(0xffffffffu, lsB, 1);
    lsB += __shfl_xor_sync(0xffffffffu, lsB, 2);
    float invA = (lsA > 0.f) ? 1.0f / lsA : 0.f;
    float invB = (lsB > 0.f) ? 1.0f / lsB : 0.f;

    size_t obase = (size_t)(b*SEQ + i0 + warp*16 + t8)*DIM + hh*DK + 2*t4;
    #pragma unroll
    for (int f = 0; f < 8; f++) {
        float o0 = O[f][0]*invA, o1 = O[f][1]*invA;
        float o2 = O[f][2]*invB, o3 = O[f][3]*invB;
        __nv_bfloat16 h0,l0,h1,l1,h2,l2,h3,l3;
        split2(o0,h0,l0); split2(o1,h1,l1); split2(o2,h2,l2); split2(o3,h3,l3);
        *(u32*)(gOh + obase + 8*f)         = packbf(h0, h1);
        *(u32*)(gOl + obase + 8*f)         = packbf(l0, l1);
        *(u32*)(gOh + obase + 8*f + 8*DIM) = packbf(h2, h3);
        *(u32*)(gOl + obase + 8*f + 8*DIM) = packbf(l2, l3);
    }
}

// ---------------------------------------------------------------------------
extern "C" void kernel_launch(void* const* d_in, const int* in_sizes, int n_in,
                              void* d_out, int out_size)
{
    const float* x  = (const float*)d_in[0];
    const float* Wq = (const float*)d_in[1];
    const float* Wk = (const float*)d_in[2];
    const float* Wv = (const float*)d_in[3];
    const float* Wo = (const float*)d_in[4];
    const int* seq_mask     = (const int*)d_in[5];
    const int* sparse_masks = (const int*)d_in[6];
    float* out = (float*)d_out;

    cudaFuncSetAttribute(proj_gemm,   cudaFuncAttributeMaxDynamicSharedMemorySize, 2*PJ_BUF);
    cudaFuncSetAttribute(attn_kernel, cudaFuncAttributeMaxDynamicSharedMemorySize, 3*AT_STG);

    mask_prep<<<SEQ/8, 256>>>(seq_mask, sparse_masks);
    conv_x<<<MT*DIM/1024, 256>>>(x);
    conv_w<<<4*DIM*DIM/1024, 256>>>(Wq, Wk, Wv, Wo);

    proj_gemm<<<dim3(MT/128, 1536/128), 256, 2*PJ_BUF>>>(nullptr, 0); // fused QKV
    attn_kernel<<<dim3(SEQ/128, BATCH*NHEAD), 256, 3*AT_STG>>>();
    proj_gemm<<<dim3(MT/128, DIM/128), 256, 2*PJ_BUF>>>(out, 1);      // O @ Wo^T
    (void)in_sizes; (void)n_in; (void)out_size;
}

// round 7
// speedup vs baseline: 5.0674x; 1.0916x over previous
#include <cuda_runtime.h>
#include <cuda_bf16.h>
#include <cuda_fp16.h>
#include <math.h>

typedef unsigned int u32;
typedef unsigned long long u64;

#define BATCH 2
#define SEQ   2048
#define DIM   512
#define NHEAD 8
#define DK    64
#define MT    (BATCH*SEQ)
#define LOG2E 1.4426950408889634f

// ---------------- global scratch (alloc-free) ------------------------------
__device__ __nv_bfloat16 gXh[MT*DIM], gXl[MT*DIM];
__device__ __nv_bfloat16 gWh[4][DIM*DIM], gWl[4][DIM*DIM];  // 0..2 = QKV (contig), 3 = O
__device__ __half gQ[MT*DIM];                // pre-scaled 0.125*log2e
__device__ __half gK[MT*DIM];
__device__ __half gV[MT*DIM];
__device__ __nv_bfloat16 gOh[MT*DIM], gOl[MT*DIM];
__device__ u32 g_mask[4*SEQ*(SEQ/32)];       // [b*2+par][row][word]

// ---------------- helpers ---------------------------------------------------
static __device__ __forceinline__ u32 smem_u32(const void* p) {
    u32 a; asm("{ .reg .u64 t; cvta.to.shared.u64 t, %1; cvt.u32.u64 %0, t; }" : "=r"(a) : "l"(p));
    return a;
}
static __device__ __forceinline__ float ex2f(float x) {
    float y; asm("ex2.approx.f32 %0, %1;" : "=f"(y) : "f"(x)); return y;
}
static __device__ __forceinline__ void split2(float v, __nv_bfloat16& hi, __nv_bfloat16& lo) {
    hi = __float2bfloat16(v);
    lo = __float2bfloat16(v - __bfloat162float(hi));
}
static __device__ __forceinline__ u32 packbf(__nv_bfloat16 a, __nv_bfloat16 b) {
    return (u32)__bfloat16_as_ushort(a) | ((u32)__bfloat16_as_ushort(b) << 16);
}
// packs {lo, hi} halves
static __device__ __forceinline__ u32 cvtf16x2(float lo, float hi) {
    u32 d; asm("cvt.rn.f16x2.f32 %0, %1, %2;" : "=r"(d) : "f"(hi), "f"(lo)); return d;
}

#define LDM4(r0,r1,r2,r3,a) \
    asm volatile("ldmatrix.sync.aligned.m8n8.x4.shared.b16 {%0,%1,%2,%3}, [%4];" \
        : "=r"(r0),"=r"(r1),"=r"(r2),"=r"(r3) : "r"(a))
#define LDM4T(r0,r1,r2,r3,a) \
    asm volatile("ldmatrix.sync.aligned.m8n8.x4.trans.shared.b16 {%0,%1,%2,%3}, [%4];" \
        : "=r"(r0),"=r"(r1),"=r"(r2),"=r"(r3) : "r"(a))
#define MMAB(d,a,b) \
    asm volatile("mma.sync.aligned.m16n8k16.row.col.f32.bf16.bf16.f32 " \
        "{%0,%1,%2,%3}, {%4,%5,%6,%7}, {%8,%9}, {%0,%1,%2,%3};" \
        : "+f"((d)[0]),"+f"((d)[1]),"+f"((d)[2]),"+f"((d)[3]) \
        : "r"((a)[0]),"r"((a)[1]),"r"((a)[2]),"r"((a)[3]),"r"((b)[0]),"r"((b)[1]))
#define MMAH(d,a,b) \
    asm volatile("mma.sync.aligned.m16n8k16.row.col.f32.f16.f16.f32 " \
        "{%0,%1,%2,%3}, {%4,%5,%6,%7}, {%8,%9}, {%0,%1,%2,%3};" \
        : "+f"((d)[0]),"+f"((d)[1]),"+f"((d)[2]),"+f"((d)[3]) \
        : "r"((a)[0]),"r"((a)[1]),"r"((a)[2]),"r"((a)[3]),"r"((b)[0]),"r"((b)[1]))

#define CPA16(d, s) asm volatile("cp.async.cg.shared.global [%0], [%1], 16;" :: "r"(d), "l"(s) : "memory")
#define CPCOMMIT()  asm volatile("cp.async.commit_group;" ::: "memory")
#define CPWAIT(n)   asm volatile("cp.async.wait_group %0;" :: "n"(n) : "memory")

// ---------------- fp32 -> (hi, lo) bf16 split: x ----------------------------
__global__ void conv_x(const float* __restrict__ src) {
    int i = (blockIdx.x * blockDim.x + threadIdx.x) * 4;
    float4 v = *(const float4*)(src + i);
    __nv_bfloat16 h0,l0,h1,l1,h2,l2,h3,l3;
    split2(v.x,h0,l0); split2(v.y,h1,l1); split2(v.z,h2,l2); split2(v.w,h3,l3);
    *(uint2*)(gXh + i) = make_uint2(packbf(h0,h1), packbf(h2,h3));
    *(uint2*)(gXl + i) = make_uint2(packbf(l0,l1), packbf(l2,l3));
}

// ---------------- fp32 -> (hi, lo) bf16 split: all 4 weights ----------------
__global__ void conv_w(const float* __restrict__ Wq, const float* __restrict__ Wk,
                       const float* __restrict__ Wv, const float* __restrict__ Wo) {
    int sel = blockIdx.x >> 8;               // 256 blocks per weight
    int blk = blockIdx.x & 255;
    const float* src = sel == 0 ? Wq : sel == 1 ? Wk : sel == 2 ? Wv : Wo;
    int i = (blk * blockDim.x + threadIdx.x) * 4;
    float4 v = *(const float4*)(src + i);
    __nv_bfloat16 h0,l0,h1,l1,h2,l2,h3,l3;
    split2(v.x,h0,l0); split2(v.y,h1,l1); split2(v.z,h2,l2); split2(v.w,h3,l3);
    *(uint2*)(gWh[sel] + i) = make_uint2(packbf(h0,h1), packbf(h2,h3));
    *(uint2*)(gWl[sel] + i) = make_uint2(packbf(l0,l1), packbf(l2,l3));
}

// ---------------- combined masks -> bit tables (row per block) --------------
__global__ void mask_prep(const int* __restrict__ seq_mask,
                          const int* __restrict__ sparse_masks) {
    int row  = blockIdx.x;
    int warp = threadIdx.x >> 5, lane = threadIdx.x & 31;
    const int* s0 = seq_mask     + (size_t)0*SEQ*SEQ + (size_t)row*SEQ;
    const int* s1 = seq_mask     + (size_t)1*SEQ*SEQ + (size_t)row*SEQ;
    const int* p0 = sparse_masks + (size_t)0*SEQ*SEQ + (size_t)row*SEQ;
    const int* p1 = sparse_masks + (size_t)1*SEQ*SEQ + (size_t)row*SEQ;
    #pragma unroll
    for (int q = 0; q < 8; q++) {
        int w = warp*8 + q;
        int j = w*32 + lane;
        int a0 = s0[j], a1 = s1[j], b0 = p0[j], b1 = p1[j];
        u32 m00 = __ballot_sync(0xffffffffu, (a0 & b0) != 0);
        u32 m01 = __ballot_sync(0xffffffffu, (a0 & b1) != 0);
        u32 m10 = __ballot_sync(0xffffffffu, (a1 & b0) != 0);
        u32 m11 = __ballot_sync(0xffffffffu, (a1 & b1) != 0);
        if (lane == 0) {
            g_mask[((size_t)0*SEQ + row)*(SEQ/32) + w] = m00;
            g_mask[((size_t)1*SEQ + row)*(SEQ/32) + w] = m01;
            g_mask[((size_t)2*SEQ + row)*(SEQ/32) + w] = m10;
            g_mask[((size_t)3*SEQ + row)*(SEQ/32) + w] = m11;
        }
    }
}

// ---------------- split-bf16 GEMM (mma.sync, cp.async DB, 64x128 tile) ------
// mode 0: A = x splits, B = QKV concat [1536][512]; epilogue -> gQ/gK/gV fp16.
// mode 1: A = O splits,  B = Wo [512][512];          epilogue -> fp32 out.
// Buffer (48KB): Ah @0 (8K), Al @8192, Bh @16384 (16K), Bl @32768.
#define PJ_BUF 49152
__global__ __launch_bounds__(256, 2) void proj_gemm(float* __restrict__ Yout, int mode) {
    extern __shared__ char dsm[];
    u32 sb = (smem_u32(dsm) + 127) & ~127u;

    const __nv_bfloat16* A_h = mode ? gOh : gXh;
    const __nv_bfloat16* A_l = mode ? gOl : gXl;
    const __nv_bfloat16* B_h = mode ? gWh[3] : gWh[0];
    const __nv_bfloat16* B_l = mode ? gWl[3] : gWl[0];

    int tid = threadIdx.x, lane = tid & 31, warp = tid >> 5;
    int t4 = lane & 3, t8 = lane >> 2;
    int mrl = lane & 7, mm = lane >> 3;
    int wm = warp & 1, wn = warp >> 1;            // 2 x 4 warps, warp tile 32x32
    int m0 = blockIdx.x * 64, n0 = blockIdx.y * 128;

    #define PJ_ISSUE(c, buf) do { \
        _Pragma("unroll") \
        for (int q = 0; q < 12; q++) { \
            int idx = tid + q*256; \
            const __nv_bfloat16* s; u32 d; \
            if (idx < 1024) { \
                int mtx = idx >> 9, rem = idx & 511, r = rem >> 3, ch = rem & 7; \
                s = (mtx ? A_l : A_h) + (size_t)(m0 + r)*DIM + (c)*64 + ch*8; \
                d = sb + (buf)*PJ_BUF + mtx*8192 + r*128 + ((ch ^ (r & 7)) << 4); \
            } else { \
                int i2 = idx - 1024; \
                int mtx = i2 >> 10, rem = i2 & 1023, r = rem >> 3, ch = rem & 7; \
                s = (mtx ? B_l : B_h) + (size_t)(n0 + r)*DIM + (c)*64 + ch*8; \
                d = sb + (buf)*PJ_BUF + 16384 + mtx*16384 + r*128 + ((ch ^ (r & 7)) << 4); \
            } \
            CPA16(d, s); \
        } \
        CPCOMMIT(); \
    } while (0)

    float C[2][4][4];
    #pragma unroll
    for (int a = 0; a < 2; a++)
        #pragma unroll
        for (int b = 0; b < 4; b++)
            #pragma unroll
            for (int c = 0; c < 4; c++) C[a][b][c] = 0.f;

    PJ_ISSUE(0, 0);
    PJ_ISSUE(1, 1);

    for (int c = 0; c < 8; c++) {
        if (c < 7) CPWAIT(1); else CPWAIT(0);
        __syncthreads();
        u32 bb = sb + (c & 1)*PJ_BUF;

        #pragma unroll
        for (int ks = 0; ks < 4; ks++) {
            u32 AH[2][4], AL[2][4], BH[4][2], BL[4][2];
            int ch = 2*ks + (mm >> 1);
            #pragma unroll
            for (int fm = 0; fm < 2; fm++) {
                int row = wm*32 + fm*16 + (mm & 1)*8 + mrl;
                u32 a = bb + row*128 + ((ch ^ (row & 7)) << 4);
                LDM4(AH[fm][0], AH[fm][1], AH[fm][2], AH[fm][3], a);
                LDM4(AL[fm][0], AL[fm][1], AL[fm][2], AL[fm][3], a + 8192);
            }
            #pragma unroll
            for (int p = 0; p < 2; p++) {
                int row = wn*32 + p*16 + (mm & 1)*8 + mrl;
                u32 a = bb + 16384 + row*128 + ((ch ^ (row & 7)) << 4);
                LDM4(BH[2*p][0], BH[2*p+1][0], BH[2*p][1], BH[2*p+1][1], a);
                LDM4(BL[2*p][0], BL[2*p+1][0], BL[2*p][1], BL[2*p+1][1], a + 16384);
            }
            #pragma unroll
            for (int fm = 0; fm < 2; fm++)
                #pragma unroll
                for (int fn = 0; fn < 4; fn++) {
                    MMAB(C[fm][fn], AH[fm], BH[fn]);
                    MMAB(C[fm][fn], AH[fm], BL[fn]);
                    MMAB(C[fm][fn], AL[fm], BH[fn]);
                }
        }
        __syncthreads();
        if (c + 2 < 8) PJ_ISSUE(c + 2, c & 1);
    }

    #pragma unroll
    for (int fm = 0; fm < 2; fm++) {
        int rA = m0 + wm*32 + fm*16 + t8;
        #pragma unroll
        for (int fn = 0; fn < 4; fn++) {
            int n = n0 + wn*32 + fn*8 + 2*t4;
            float c0 = C[fm][fn][0], c1 = C[fm][fn][1];
            float c2 = C[fm][fn][2], c3 = C[fm][fn][3];
            if (mode) {
                *(float2*)(Yout + (size_t)rA*DIM + n)     = make_float2(c0, c1);
                *(float2*)(Yout + (size_t)(rA+8)*DIM + n) = make_float2(c2, c3);
            } else {
                int osel = n >> 9, col = n & 511;
                __half* dst = osel == 0 ? gQ : osel == 1 ? gK : gV;
                float sc = osel == 0 ? 0.125f * LOG2E : 1.f;
                *(u32*)(dst + (size_t)rA*DIM + col)     = cvtf16x2(c0*sc, c1*sc);
                *(u32*)(dst + (size_t)(rA+8)*DIM + col) = cvtf16x2(c2*sc, c3*sc);
            }
        }
    }
}

// ---------------- flash attention (fp16 mma, 3-stage cp.async) --------------
// CTA: 128 i-rows of one (b,h); 8 warps x 16 rows; 32 j-tiles of 64.
// Single-fp16 K and V: S = Q K^T (1 group), O += P V (1 group).
#define AT_STG 16384   // per stage: K 8KB @0, V 8KB @8192
__global__ __launch_bounds__(256, 2) void attn_kernel() {
    extern __shared__ char dsm[];
    u32 sb = (smem_u32(dsm) + 127) & ~127u;

    int tid = threadIdx.x, lane = tid & 31, warp = tid >> 5;
    int t4 = lane & 3, t8 = lane >> 2;
    int mrl = lane & 7, mm = lane >> 3;
    int i0 = blockIdx.x * 128;
    int bh = blockIdx.y, b = bh >> 3, hh = bh & 7;
    int combo = b*2 + (hh & 1);

    #define AT_ISSUE(jt, st) do { \
        _Pragma("unroll") \
        for (int q = 0; q < 4; q++) { \
            int idx = tid + q*256; \
            int mtx = idx >> 9, rem = idx & 511, r = rem >> 3, ch = rem & 7; \
            const __half* s = (mtx ? gV : gK) + (size_t)(b*SEQ + (jt)*64 + r)*DIM + hh*DK + ch*8; \
            u32 d = sb + (st)*AT_STG + mtx*8192 + r*128 + ((ch ^ (r & 7)) << 4); \
            CPA16(d, s); \
        } \
        CPCOMMIT(); \
    } while (0)

    AT_ISSUE(0, 0);
    AT_ISSUE(1, 1);
    AT_ISSUE(2, 2);

    // Q fragments (fp16) held in registers for the whole kernel
    u32 QA[4][4];
    {
        size_t qbase = (size_t)(b*SEQ + i0 + warp*16 + t8)*DIM + hh*DK + 2*t4;
        #pragma unroll
        for (int ks = 0; ks < 4; ks++) {
            QA[ks][0] = *(const u32*)(gQ + qbase + ks*16);
            QA[ks][1] = *(const u32*)(gQ + qbase + ks*16 + 8*DIM);
            QA[ks][2] = *(const u32*)(gQ + qbase + ks*16 + 8);
            QA[ks][3] = *(const u32*)(gQ + qbase + ks*16 + 8*DIM + 8);
        }
    }

    const u32* mrowA = g_mask + ((size_t)combo*SEQ + i0 + warp*16 + t8)*(SEQ/32);
    const u32* mrowB = mrowA + 8*(SEQ/32);

    float O[8][4];
    #pragma unroll
    for (int f = 0; f < 8; f++)
        #pragma unroll
        for (int c = 0; c < 4; c++) O[f][c] = 0.f;
    float lsA = 0.f, lsB = 0.f;

    int stage = 0;
    for (int t = 0; t < 32; t++) {
        if (t <= 29) CPWAIT(2); else if (t == 30) CPWAIT(1); else CPWAIT(0);
        __syncthreads();
        u32 kb = sb + stage*AT_STG;
        u32 vb = kb + 8192;

        // mask words early (LDG hidden under S MMAs)
        uint2 wA = *(const uint2*)(mrowA + (t << 1));
        uint2 wB = *(const uint2*)(mrowB + (t << 1));

        // S = Q K^T
        float S[8][4];
        #pragma unroll
        for (int f = 0; f < 8; f++)
            #pragma unroll
            for (int c = 0; c < 4; c++) S[f][c] = 0.f;

        #pragma unroll
        for (int ks = 0; ks < 4; ks++) {
            u32 BH[8][2];
            int ch = 2*ks + (mm >> 1);
            #pragma unroll
            for (int p = 0; p < 4; p++) {
                int row = 16*p + (mm & 1)*8 + mrl;
                u32 a = kb + row*128 + ((ch ^ (row & 7)) << 4);
                LDM4(BH[2*p][0], BH[2*p+1][0], BH[2*p][1], BH[2*p+1][1], a);
            }
            #pragma unroll
            for (int f = 0; f < 8; f++) MMAH(S[f], QA[ks], BH[f]);
        }

        // mask + ex2 + pack P to fp16 A-fragments (registers only)
        u64 mwA = (u64)wA.x | ((u64)wA.y << 32);
        u64 mwB = (u64)wB.x | ((u64)wB.y << 32);

        u32 PH[4][4];
        #pragma unroll
        for (int f = 0; f < 8; f++) {
            int sh = 8*f + 2*t4;
            u32 bA = (u32)(mwA >> sh);
            u32 bB = (u32)(mwB >> sh);
            float p0 = (bA & 1u) ? ex2f(S[f][0]) : 0.f;
            float p1 = (bA & 2u) ? ex2f(S[f][1]) : 0.f;
            float p2 = (bB & 1u) ? ex2f(S[f][2]) : 0.f;
            float p3 = (bB & 2u) ? ex2f(S[f][3]) : 0.f;
            lsA += p0 + p1;
            lsB += p2 + p3;
            int ks = f >> 1, o = (f & 1)*2;
            PH[ks][o]   = cvtf16x2(p0, p1);
            PH[ks][o+1] = cvtf16x2(p2, p3);
        }

        // O += P V  (V fragments via ldmatrix.trans)
        #pragma unroll
        for (int ks = 0; ks < 4; ks++) {
            u32 VH[8][2];
            int row = 16*ks + (mm >> 1)*8 + mrl;
            #pragma unroll
            for (int p = 0; p < 4; p++) {
                int ch = 2*p + (mm & 1);
                u32 a = vb + row*128 + ((ch ^ (row & 7)) << 4);
                LDM4T(VH[2*p][0], VH[2*p+1][0], VH[2*p][1], VH[2*p+1][1], a);
            }
            #pragma unroll
            for (int f = 0; f < 8; f++) MMAH(O[f], PH[ks], VH[f]);
        }
        __syncthreads();
        if (t + 3 < 32) AT_ISSUE(t + 3, stage);
        stage = (stage == 2) ? 0 : stage + 1;
    }

    // reduce row sums across the 4 lanes sharing each row, normalize, store
    lsA += __shfl_xor_sync(0xffffffffu, lsA, 1);
    lsA += __shfl_xor_sync(0xffffffffu, lsA, 2);
    lsB += __shfl_xor_sync(0xffffffffu, lsB, 1);
    lsB += __shfl_xor_sync(0xffffffffu, lsB, 2);
    float invA = (lsA > 0.f) ? 1.0f / lsA : 0.f;
    float invB = (lsB > 0.f) ? 1.0f / lsB : 0.f;

    size_t obase = (size_t)(b*SEQ + i0 + warp*16 + t8)*DIM + hh*DK + 2*t4;
    #pragma unroll
    for (int f = 0; f < 8; f++) {
        float o0 = O[f][0]*invA, o1 = O[f][1]*invA;
        float o2 = O[f][2]*invB, o3 = O[f][3]*invB;
        __nv_bfloat16 h0,l0,h1,l1,h2,l2,h3,l3;
        split2(o0,h0,l0); split2(o1,h1,l1); split2(o2,h2,l2); split2(o3,h3,l3);
        *(u32*)(gOh + obase + 8*f)         = packbf(h0, h1);
        *(u32*)(gOl + obase + 8*f)         = packbf(l0, l1);
        *(u32*)(gOh + obase + 8*f + 8*DIM) = packbf(h2, h3);
        *(u32*)(gOl + obase + 8*f + 8*DIM) = packbf(l2, l3);
    }
}

// ---------------------------------------------------------------------------
extern "C" void kernel_launch(void* const* d_in, const int* in_sizes, int n_in,
                              void* d_out, int out_size)
{
    const float* x  = (const float*)d_in[0];
    const float* Wq = (const float*)d_in[1];
    const float* Wk = (const float*)d_in[2];
    const float* Wv = (const float*)d_in[3];
    const float* Wo = (const float*)d_in[4];
    const int* seq_mask     = (const int*)d_in[5];
    const int* sparse_masks = (const int*)d_in[6];
    float* out = (float*)d_out;

    cudaFuncSetAttribute(proj_gemm,   cudaFuncAttributeMaxDynamicSharedMemorySize, 2*PJ_BUF);
    cudaFuncSetAttribute(attn_kernel, cudaFuncAttributeMaxDynamicSharedMemorySize, 3*AT_STG);

    mask_prep<<<SEQ, 256>>>(seq_mask, sparse_masks);
    conv_x<<<MT*DIM/1024, 256>>>(x);
    conv_w<<<4*DIM*DIM/1024, 256>>>(Wq, Wk, Wv, Wo);

    proj_gemm<<<dim3(MT/64, 1536/128), 256, 2*PJ_BUF>>>(nullptr, 0); // fused QKV
    attn_kernel<<<dim3(SEQ/128, BATCH*NHEAD), 256, 3*AT_STG>>>();
    proj_gemm<<<dim3(MT/64, DIM/128), 256, 2*PJ_BUF>>>(out, 1);      // O @ Wo^T
    (void)in_sizes; (void)n_in; (void)out_size;
}